// round 3
// baseline (speedup 1.0000x reference)
#include <cuda_runtime.h>
#include <cuda_bf16.h>
#include <math.h>
#include <stdint.h>

#define BATCH 32
#define L0    2048
#define CIN   7
#define DM    512
#define DFF_  2048
#define NH    8
#define DH    64
#define POUT  96

// ---------------- scratch (static device globals; no allocation) ----------------
__device__ __align__(128) float g_h[(size_t)BATCH*L0*DM];
__device__ __align__(128) float g_q[(size_t)BATCH*L0*DM];
__device__ __align__(128) float g_k[(size_t)BATCH*L0*DM];
__device__ __align__(128) float g_v[(size_t)BATCH*L0*DM];
__device__ __align__(128) float g_c[(size_t)BATCH*L0*DM];
__device__ __align__(128) float g_f[(size_t)BATCH*L0*DFF_];
__device__ __align__(128) float g_m[(size_t)BATCH*NH*L0];
__device__ __align__(128) int   g_top[BATCH*NH*64];
__device__ __align__(128) float g_vmean[BATCH*NH*DH];
__device__ __align__(128) int   g_idx[L0*38 + 1024*34 + 512*31];
__device__ __align__(128) float g_stats[2*64*DM];
__device__ __align__(128) float g_bnsc[DM];
__device__ __align__(128) float g_bnsh[DM];

// ---------------- threefry2x32 (JAX-compatible, 20 rounds) ----------------
__host__ __device__ inline void tf2x32(unsigned k0, unsigned k1, unsigned c0, unsigned c1,
                                       unsigned& o0, unsigned& o1)
{
    unsigned ks0 = k0, ks1 = k1, ks2 = k0 ^ k1 ^ 0x1BD11BDAu;
    unsigned x0 = c0 + ks0, x1 = c1 + ks1;
#define TFR(r) { x0 += x1; x1 = (x1 << (r)) | (x1 >> (32 - (r))); x1 ^= x0; }
    TFR(13) TFR(15) TFR(26) TFR(6)   x0 += ks1; x1 += ks2 + 1u;
    TFR(17) TFR(29) TFR(16) TFR(24)  x0 += ks2; x1 += ks0 + 2u;
    TFR(13) TFR(15) TFR(26) TFR(6)   x0 += ks0; x1 += ks1 + 3u;
    TFR(17) TFR(29) TFR(16) TFR(24)  x0 += ks1; x1 += ks2 + 4u;
    TFR(13) TFR(15) TFR(26) TFR(6)   x0 += ks2; x1 += ks0 + 5u;
#undef TFR
    o0 = x0; o1 = x1;
}

// randint(key,(L,u),0,L) with L=2^p reduces to lower_bits & (L-1), where
// lower_bits come from k2 = split(fold_in(key(42), layer))[1].
// threefry_partitionable: bits[p] = (v0 ^ v1) of cipher(k2, (0, p)).
__global__ void idx_k(unsigned ka, unsigned kb, int n, unsigned mask, int* __restrict__ out)
{
    int i = blockIdx.x * 256 + threadIdx.x;
    if (i >= n) return;
    unsigned v0, v1;
    tf2x32(ka, kb, 0u, (unsigned)i, v0, v1);
    out[i] = (int)((v0 ^ v1) & mask);
}

// ---------------- token conv (circular, no bias) + positional embedding ----------------
__global__ void tokconv_k(const float* __restrict__ x, const float* __restrict__ w,
                          float* __restrict__ h)
{
    int l = blockIdx.x, b = blockIdx.y;
    int d = threadIdx.x; // 512
    __shared__ float sx[3][CIN];
    if (threadIdx.x < 21) {
        int t = threadIdx.x / 7, c = threadIdx.x % 7;
        int ls = l + t - 1; if (ls < 0) ls += L0; if (ls >= L0) ls -= L0;
        sx[t][c] = x[((size_t)b*L0 + ls)*CIN + c];
    }
    __syncthreads();
    float acc = 0.f;
    const float* wd = w + d*CIN*3;  // (D, CIN, 3)
#pragma unroll
    for (int c = 0; c < CIN; c++)
#pragma unroll
        for (int t = 0; t < 3; t++)
            acc += sx[t][c] * wd[c*3 + t];
    int i2 = d & ~1;
    float freq = expf((float)i2 * (-9.210340371976184f / 512.0f)); // -log(1e4)/D
    float ang = (float)l * freq;
    float pe = (d & 1) ? cosf(ang) : sinf(ang);
    h[((size_t)b*L0 + l)*DM + d] = acc + pe;
}

// ---------------- SGEMM: C = act(A[M,K] @ W[N,K]^T + bias) (+R) ----------------
#define BM 64
#define BN 64
#define BKk 16
// MODE: 0 plain+bias, 1 bias+gelu(exact), 2 bias+residual
template<int MODE>
__global__ void gemm_k(const float* __restrict__ A, const float* __restrict__ W,
                       const float* __restrict__ bias, const float* __restrict__ R,
                       float* __restrict__ C, int M, int N, int K)
{
    __shared__ __align__(16) float As[BKk][BM];
    __shared__ __align__(16) float Ws[BKk][BN];
    int tid = threadIdx.x;
    int m0 = blockIdx.y * BM, n0 = blockIdx.x * BN;
    int lrow = tid >> 2;
    int lc4  = (tid & 3) * 4;
    int ty = tid >> 4, tx = tid & 15;
    float acc[4][4] = {};
    for (int k0 = 0; k0 < K; k0 += BKk) {
        float4 av = *(const float4*)&A[(size_t)(m0 + lrow)*K + k0 + lc4];
        float4 wv = *(const float4*)&W[(size_t)(n0 + lrow)*K + k0 + lc4];
        As[lc4+0][lrow] = av.x; As[lc4+1][lrow] = av.y; As[lc4+2][lrow] = av.z; As[lc4+3][lrow] = av.w;
        Ws[lc4+0][lrow] = wv.x; Ws[lc4+1][lrow] = wv.y; Ws[lc4+2][lrow] = wv.z; Ws[lc4+3][lrow] = wv.w;
        __syncthreads();
#pragma unroll
        for (int kk = 0; kk < BKk; kk++) {
            float a[4], bb[4];
            *(float4*)a  = *(const float4*)&As[kk][ty*4];
            *(float4*)bb = *(const float4*)&Ws[kk][tx*4];
#pragma unroll
            for (int i = 0; i < 4; i++)
#pragma unroll
                for (int j = 0; j < 4; j++)
                    acc[i][j] += a[i]*bb[j];
        }
        __syncthreads();
    }
#pragma unroll
    for (int i = 0; i < 4; i++) {
        int m = m0 + ty*4 + i;
#pragma unroll
        for (int j = 0; j < 4; j++) {
            int n = n0 + tx*4 + j;
            float cv = acc[i][j] + bias[n];
            if (MODE == 1) cv = 0.5f * cv * (1.0f + erff(cv * 0.7071067811865475f));
            if (MODE == 2) cv += R[(size_t)m*N + n];
            C[(size_t)m*N + n] = cv;
        }
    }
}

// ---------------- ProbSparse: sampled m = max - mean ----------------
__global__ void sample_m_k(const float* __restrict__ Q, const float* __restrict__ Km,
                           const int* __restrict__ idx, float* __restrict__ Mout,
                           int L, int U)
{
    int b = blockIdx.z, h = blockIdx.y;
    int w = threadIdx.x >> 5, lane = threadIdx.x & 31;
    int l = blockIdx.x * 8 + w;
    float2 q2 = *(const float2*)(Q + ((size_t)b*L + l)*DM + h*DH + 2*lane);
    float mx = -INFINITY, sm = 0.f;
    const int* ip = idx + (size_t)l * U;
    for (int j = 0; j < U; j++) {
        int r = ip[j];
        float2 k2 = *(const float2*)(Km + ((size_t)b*L + r)*DM + h*DH + 2*lane);
        float p = q2.x*k2.x + q2.y*k2.y;
#pragma unroll
        for (int o = 16; o > 0; o >>= 1) p += __shfl_xor_sync(0xffffffffu, p, o);
        mx = fmaxf(mx, p); sm += p;
    }
    if (lane == 0) Mout[((size_t)b*NH + h)*L + l] = mx - sm / (float)U;
}

// ---------------- iterative top-u per (b,h), ties -> smallest index ----------------
__global__ void topk_k(const float* __restrict__ Min, int* __restrict__ top, int L, int U)
{
    __shared__ float sv[2048];
    __shared__ float rv[256];
    __shared__ int   ri[256];
    int bh = blockIdx.x, tid = threadIdx.x;
    const float* mp = Min + (size_t)bh * L;
    for (int i = tid; i < L; i += 256) sv[i] = mp[i];
    __syncthreads();
    for (int t = 0; t < U; t++) {
        float bv = -INFINITY; int bi = 0x7fffffff;
        for (int i = tid; i < L; i += 256) {
            float v = sv[i];
            if (v > bv || (v == bv && i < bi)) { bv = v; bi = i; }
        }
        rv[tid] = bv; ri[tid] = bi;
        __syncthreads();
        for (int s = 128; s > 0; s >>= 1) {
            if (tid < s) {
                if (rv[tid+s] > rv[tid] || (rv[tid+s] == rv[tid] && ri[tid+s] < ri[tid])) {
                    rv[tid] = rv[tid+s]; ri[tid] = ri[tid+s];
                }
            }
            __syncthreads();
        }
        if (tid == 0) { top[(size_t)bh*U + t] = ri[0]; sv[ri[0]] = -INFINITY; }
        __syncthreads();
    }
}

// ---------------- mean of V over L per (b,h,d) ----------------
__global__ void vmean_k(const float* __restrict__ V, float* __restrict__ out, int L)
{
    int b = blockIdx.y, h = blockIdx.x;
    int tid = threadIdx.x;
    int d = tid & 63, g = tid >> 6;
    __shared__ float red[4][64];
    float s = 0.f;
    for (int l = g; l < L; l += 4)
        s += V[((size_t)b*L + l)*DM + h*DH + d];
    red[g][d] = s;
    __syncthreads();
    if (g == 0)
        out[((size_t)b*NH + h)*DH + d] = (red[0][d]+red[1][d]+red[2][d]+red[3][d]) / (float)L;
}

__global__ void fillctx_k(const float* __restrict__ vm, float* __restrict__ ctx, int L)
{
    size_t i = (size_t)blockIdx.x * 256 + threadIdx.x;
    int d = (int)(i & 511);
    size_t bl = i >> 9;
    int b = (int)(bl / (size_t)L);
    int h = d >> 6, dd = d & 63;
    ctx[i] = vm[((size_t)b*NH + h)*DH + dd];
}

// ---------------- full attention for the u selected queries ----------------
__global__ void attn_top_k(const float* __restrict__ Q, const float* __restrict__ Km,
                           const float* __restrict__ V, const int* __restrict__ top,
                           float* __restrict__ ctx, int L, int U)
{
    __shared__ float sc[2048];
    __shared__ float wred[8];
    __shared__ float r2[256];
    __shared__ float fred[4][64];
    __shared__ float s_max;
    int b = blockIdx.z, h = blockIdx.y, j = blockIdx.x;
    int tid = threadIdx.x, w = tid >> 5, lane = tid & 31;
    int t = top[((size_t)b*NH + h)*U + j];
    float2 q2 = *(const float2*)(Q + ((size_t)b*L + t)*DM + h*DH + 2*lane);
    float wmax = -INFINITY;
    for (int r = w; r < L; r += 8) {
        float2 k2 = *(const float2*)(Km + ((size_t)b*L + r)*DM + h*DH + 2*lane);
        float p = q2.x*k2.x + q2.y*k2.y;
#pragma unroll
        for (int o = 16; o > 0; o >>= 1) p += __shfl_xor_sync(0xffffffffu, p, o);
        p *= 0.125f; // 1/sqrt(64)
        if (lane == 0) sc[r] = p;
        wmax = fmaxf(wmax, p);
    }
    if (lane == 0) wred[w] = wmax;
    __syncthreads();
    if (tid == 0) {
        float mm = wred[0];
        for (int i2 = 1; i2 < 8; i2++) mm = fmaxf(mm, wred[i2]);
        s_max = mm;
    }
    __syncthreads();
    float mxv = s_max, ls = 0.f;
    for (int r = tid; r < L; r += 256) { float e = expf(sc[r] - mxv); sc[r] = e; ls += e; }
    r2[tid] = ls;
    __syncthreads();
    for (int s = 128; s > 0; s >>= 1) { if (tid < s) r2[tid] += r2[tid+s]; __syncthreads(); }
    float inv = 1.0f / r2[0];
    int d = tid & 63, g = tid >> 6;
    float acc = 0.f;
    for (int r = g; r < L; r += 4)
        acc += sc[r] * V[((size_t)b*L + r)*DM + h*DH + d];
    fred[g][d] = acc;
    __syncthreads();
    if (g == 0)
        ctx[((size_t)b*L + t)*DM + h*DH + d] =
            (fred[0][d] + fred[1][d] + fred[2][d] + fred[3][d]) * inv;
}

// ---------------- LayerNorm: out = (x-mu)/sqrt(var+eps)*g + b ----------------
__global__ void ln_k(const float* __restrict__ in, const float* __restrict__ g,
                     const float* __restrict__ be, float* __restrict__ out)
{
    __shared__ float red[512];
    __shared__ float s_mu, s_rstd;
    int d = threadIdx.x; size_t row = blockIdx.x;
    float v = in[row*DM + d];
    red[d] = v; __syncthreads();
    for (int s = 256; s > 0; s >>= 1) { if (d < s) red[d] += red[d+s]; __syncthreads(); }
    if (d == 0) s_mu = red[0] * (1.0f/512.0f);
    __syncthreads();
    float w = v - s_mu;
    red[d] = w*w; __syncthreads();
    for (int s = 256; s > 0; s >>= 1) { if (d < s) red[d] += red[d+s]; __syncthreads(); }
    if (d == 0) s_rstd = rsqrtf(red[0] * (1.0f/512.0f) + 1e-5f);
    __syncthreads();
    out[row*DM + d] = w * s_rstd * g[d] + be[d];
}

// ---------------- im2col for circular distilling conv, col = c*3+t ----------------
__global__ void im2col_k(const float* __restrict__ h, float* __restrict__ A2, int L)
{
    size_t i = (size_t)blockIdx.x * 256 + threadIdx.x;
    if (i >= (size_t)BATCH * L * 1536) return;
    int j = (int)(i % 1536);
    size_t bl = i / 1536;
    int b = (int)(bl / (size_t)L), l = (int)(bl % (size_t)L);
    int c = j / 3, t = j % 3;
    int ls = l + t - 1; if (ls < 0) ls += L; if (ls >= L) ls -= L;
    A2[i] = h[((size_t)b*L + ls)*DM + c];
}

// ---------------- BatchNorm stats over (B,L) ----------------
__global__ void bnstat1_k(const float* __restrict__ y, float* __restrict__ st, int M)
{
    int d = threadIdx.x, chunk = blockIdx.x;
    int rows = M / 64;
    const float* p = y + (size_t)chunk * rows * DM;
    float s = 0.f, s2 = 0.f;
    for (int r = 0; r < rows; r++) { float v = p[(size_t)r*DM + d]; s += v; s2 += v*v; }
    st[chunk*DM + d] = s;
    st[64*DM + chunk*DM + d] = s2;
}

__global__ void bnstat2_k(const float* __restrict__ st, const float* __restrict__ g,
                          const float* __restrict__ be, float* __restrict__ sc,
                          float* __restrict__ sh, int M)
{
    int d = threadIdx.x;
    float s = 0.f, s2 = 0.f;
    for (int c = 0; c < 64; c++) { s += st[c*DM + d]; s2 += st[64*DM + c*DM + d]; }
    float mu = s / (float)M;
    float var = s2 / (float)M - mu*mu;
    float scale = g[d] * rsqrtf(var + 1e-5f);
    sc[d] = scale; sh[d] = be[d] - mu*scale;
}

// ---------------- BN-normalize + ELU + maxpool(3, stride2, -inf pad) ----------------
__global__ void pool_k(const float* __restrict__ y, const float* __restrict__ sc,
                       const float* __restrict__ sh, float* __restrict__ out, int L)
{
    int d = threadIdx.x, j = blockIdx.x, b = blockIdx.y;
    int Lh = L / 2;
    float scl = sc[d], shf = sh[d];
    float m = -INFINITY;
#pragma unroll
    for (int t = 0; t < 3; t++) {
        int ly = 2*j - 1 + t;
        if (ly < 0 || ly >= L) continue;
        float v = y[((size_t)b*L + ly)*DM + d] * scl + shf;
        v = v > 0.f ? v : expm1f(v);
        m = fmaxf(m, v);
    }
    out[((size_t)b*Lh + j)*DM + d] = m;
}

// ---------------- final LN(row L-1) @ proj + skip ----------------
__global__ void final_k(const float* __restrict__ h, const float* __restrict__ g,
                        const float* __restrict__ be, const float* __restrict__ pw,
                        const float* __restrict__ pb, const float* __restrict__ x,
                        const float* __restrict__ sw, const float* __restrict__ sb,
                        float* __restrict__ out, int L)
{
    __shared__ float red[512];
    __shared__ float sval[512];
    __shared__ float s_mu, s_rstd;
    int d = threadIdx.x, b = blockIdx.x;
    float v = h[((size_t)b*L + (L-1))*DM + d];
    red[d] = v; __syncthreads();
    for (int s = 256; s > 0; s >>= 1) { if (d < s) red[d] += red[d+s]; __syncthreads(); }
    if (d == 0) s_mu = red[0] * (1.0f/512.0f);
    __syncthreads();
    float w = v - s_mu;
    red[d] = w*w; __syncthreads();
    for (int s = 256; s > 0; s >>= 1) { if (d < s) red[d] += red[d+s]; __syncthreads(); }
    if (d == 0) s_rstd = rsqrtf(red[0] * (1.0f/512.0f) + 1e-5f);
    __syncthreads();
    sval[d] = w * s_rstd * g[d] + be[d];
    __syncthreads();
    if (d < POUT) {
        float acc = pb[d];
        for (int kk = 0; kk < 512; kk++) acc += sval[kk] * pw[d*512 + kk];
        float sk = sb[d];
        for (int cc = 0; cc < CIN; cc++)
            sk += x[((size_t)b*L0 + (L0-1))*CIN + cc] * sw[d*CIN + cc];
        out[b*POUT + d] = acc + sk;
    }
}

extern "C" void kernel_launch(void* const* d_in, const int* in_sizes, int n_in,
                              void* d_out, int out_size)
{
    (void)in_sizes; (void)n_in; (void)out_size;
    const float* x       = (const float*)d_in[0];
    const float* skip_w  = (const float*)d_in[1];
    const float* skip_b  = (const float*)d_in[2];
    const float* tconv_w = (const float*)d_in[3];
    const float* wq = (const float*)d_in[4];  const float* bq = (const float*)d_in[5];
    const float* wk = (const float*)d_in[6];  const float* bk = (const float*)d_in[7];
    const float* wv = (const float*)d_in[8];  const float* bv = (const float*)d_in[9];
    const float* wo = (const float*)d_in[10]; const float* bo = (const float*)d_in[11];
    const float* w1 = (const float*)d_in[12]; const float* b1 = (const float*)d_in[13];
    const float* w2 = (const float*)d_in[14]; const float* b2 = (const float*)d_in[15];
    const float* ln1_g = (const float*)d_in[16]; const float* ln1_b = (const float*)d_in[17];
    const float* ln2_g = (const float*)d_in[18]; const float* ln2_b = (const float*)d_in[19];
    const float* dc_w = (const float*)d_in[20]; const float* dc_b = (const float*)d_in[21];
    const float* bn_g = (const float*)d_in[22]; const float* bn_b = (const float*)d_in[23];
    const float* fln_g = (const float*)d_in[24]; const float* fln_b = (const float*)d_in[25];
    const float* proj_w = (const float*)d_in[26]; const float* proj_b = (const float*)d_in[27];
    float* out = (float*)d_out;

    float *h, *q, *k, *v, *c, *f, *m, *vm, *stats, *bnsc, *bnsh;
    int *idx, *topI;
    cudaGetSymbolAddress((void**)&h, g_h);
    cudaGetSymbolAddress((void**)&q, g_q);
    cudaGetSymbolAddress((void**)&k, g_k);
    cudaGetSymbolAddress((void**)&v, g_v);
    cudaGetSymbolAddress((void**)&c, g_c);
    cudaGetSymbolAddress((void**)&f, g_f);
    cudaGetSymbolAddress((void**)&m, g_m);
    cudaGetSymbolAddress((void**)&vm, g_vmean);
    cudaGetSymbolAddress((void**)&stats, g_stats);
    cudaGetSymbolAddress((void**)&bnsc, g_bnsc);
    cudaGetSymbolAddress((void**)&bnsh, g_bnsh);
    cudaGetSymbolAddress((void**)&idx, g_idx);
    cudaGetSymbolAddress((void**)&topI, g_top);

    // token conv + positional embedding
    tokconv_k<<<dim3(L0, BATCH), DM>>>(x, tconv_w, h);

    int L = L0;
    const int Uarr[3] = {38, 34, 31};
    int idx_off = 0;
    for (int i = 0; i < 3; i++) {
        int U = Uarr[i];
        int M = BATCH * L;
        // RNG chain: fk = fold_in(key(42), i) = cipher((0,42),(0,i));
        // randint internally splits: k2 = split(fk)[1] = cipher(fk,(0,1)) [partitionable];
        // lower_bits[p] = x0^x1 of cipher(k2,(0,p)); idx = lower_bits & (L-1).
        unsigned fk0, fk1, s2a, s2b;
        tf2x32(0u, 42u, 0u, (unsigned)i, fk0, fk1);
        tf2x32(fk0, fk1, 0u, 1u, s2a, s2b);
        int n = L * U;
        idx_k<<<(n + 255)/256, 256>>>(s2a, s2b, n, (unsigned)(L - 1), idx + idx_off);

        // Q, K, V projections
        gemm_k<0><<<dim3(DM/BN, M/BM), 256>>>(h, wq + (size_t)i*DM*DM, bq + i*DM, nullptr, q, M, DM, DM);
        gemm_k<0><<<dim3(DM/BN, M/BM), 256>>>(h, wk + (size_t)i*DM*DM, bk + i*DM, nullptr, k, M, DM, DM);
        gemm_k<0><<<dim3(DM/BN, M/BM), 256>>>(h, wv + (size_t)i*DM*DM, bv + i*DM, nullptr, v, M, DM, DM);

        // ProbSparse attention
        sample_m_k<<<dim3(L/8, NH, BATCH), 256>>>(q, k, idx + idx_off, m, L, U);
        topk_k<<<BATCH*NH, 256>>>(m, topI, L, U);
        vmean_k<<<dim3(NH, BATCH), 256>>>(v, vm, L);
        fillctx_k<<<(unsigned)(((size_t)M*DM)/256), 256>>>(vm, c, L);
        attn_top_k<<<dim3(U, NH, BATCH), 256>>>(q, k, v, topI, c, L, U);

        // WO projection + residual (in-place into h)
        gemm_k<2><<<dim3(DM/BN, M/BM), 256>>>(c, wo + (size_t)i*DM*DM, bo + i*DM, h, h, M, DM, DM);

        // FFN
        ln_k<<<M, DM>>>(h, ln1_g + i*DM, ln1_b + i*DM, c);
        gemm_k<1><<<dim3(DFF_/BN, M/BM), 256>>>(c, w1 + (size_t)i*DFF_*DM, b1 + i*DFF_, nullptr, f, M, DFF_, DM);
        gemm_k<2><<<dim3(DM/BN, M/BM), 256>>>(f, w2 + (size_t)i*DM*DFF_, b2 + i*DM, h, c, M, DM, DFF_);
        ln_k<<<M, DM>>>(c, ln2_g + i*DM, ln2_b + i*DM, h);

        // distilling conv layer
        if (i < 2) {
            im2col_k<<<(unsigned)(((size_t)M*1536 + 255)/256), 256>>>(h, f, L);
            gemm_k<0><<<dim3(DM/BN, M/BM), 256>>>(f, dc_w + (size_t)i*DM*1536, dc_b + i*DM, nullptr, c, M, DM, 1536);
            bnstat1_k<<<64, DM>>>(c, stats, M);
            bnstat2_k<<<1, DM>>>(stats, bn_g + i*DM, bn_b + i*DM, bnsc, bnsh, M);
            pool_k<<<dim3(L/2, BATCH), DM>>>(c, bnsc, bnsh, h, L);
            L /= 2;
        }
        idx_off += n;
    }

    final_k<<<BATCH, DM>>>(h, fln_g, fln_b, proj_w, proj_b, x, skip_w, skip_b, out, L);
}

// round 4
// speedup vs baseline: 2.4194x; 2.4194x over previous
#include <cuda_runtime.h>
#include <cuda_bf16.h>
#include <math.h>
#include <stdint.h>

#define BATCH 32
#define L0    2048
#define CIN   7
#define DM    512
#define DFF_  2048
#define NH    8
#define DH    64
#define POUT  96

// ---------------- scratch (static device globals; no allocation) ----------------
__device__ __align__(128) float g_h[(size_t)BATCH*L0*DM];
__device__ __align__(128) float g_q[(size_t)BATCH*L0*DM];
__device__ __align__(128) float g_k[(size_t)BATCH*L0*DM];
__device__ __align__(128) float g_v[(size_t)BATCH*L0*DM];
__device__ __align__(128) float g_c[(size_t)BATCH*L0*DM];
__device__ __align__(128) float g_f[(size_t)BATCH*L0*DFF_];
__device__ __align__(128) float g_m[(size_t)BATCH*NH*L0];
__device__ __align__(128) int   g_top[BATCH*NH*64];
__device__ __align__(128) float g_vmean[BATCH*NH*DH];
__device__ __align__(128) int   g_idx[L0*38 + 1024*34 + 512*31];
__device__ __align__(128) float g_stats[2*64*DM];
__device__ __align__(128) float g_bnsc[DM];
__device__ __align__(128) float g_bnsh[DM];

// ---------------- threefry2x32 (JAX-compatible, 20 rounds) ----------------
__host__ __device__ inline void tf2x32(unsigned k0, unsigned k1, unsigned c0, unsigned c1,
                                       unsigned& o0, unsigned& o1)
{
    unsigned ks0 = k0, ks1 = k1, ks2 = k0 ^ k1 ^ 0x1BD11BDAu;
    unsigned x0 = c0 + ks0, x1 = c1 + ks1;
#define TFR(r) { x0 += x1; x1 = (x1 << (r)) | (x1 >> (32 - (r))); x1 ^= x0; }
    TFR(13) TFR(15) TFR(26) TFR(6)   x0 += ks1; x1 += ks2 + 1u;
    TFR(17) TFR(29) TFR(16) TFR(24)  x0 += ks2; x1 += ks0 + 2u;
    TFR(13) TFR(15) TFR(26) TFR(6)   x0 += ks0; x1 += ks1 + 3u;
    TFR(17) TFR(29) TFR(16) TFR(24)  x0 += ks1; x1 += ks2 + 4u;
    TFR(13) TFR(15) TFR(26) TFR(6)   x0 += ks2; x1 += ks0 + 5u;
#undef TFR
    o0 = x0; o1 = x1;
}

__global__ void idx_k(unsigned ka, unsigned kb, int n, unsigned mask, int* __restrict__ out)
{
    int i = blockIdx.x * 256 + threadIdx.x;
    if (i >= n) return;
    unsigned v0, v1;
    tf2x32(ka, kb, 0u, (unsigned)i, v0, v1);
    out[i] = (int)((v0 ^ v1) & mask);
}

// ---------------- token conv (circular, no bias) + positional embedding ----------------
__global__ void tokconv_k(const float* __restrict__ x, const float* __restrict__ w,
                          float* __restrict__ h)
{
    int l = blockIdx.x, b = blockIdx.y;
    int d = threadIdx.x; // 512
    __shared__ float sx[3][CIN];
    if (threadIdx.x < 21) {
        int t = threadIdx.x / 7, c = threadIdx.x % 7;
        int ls = l + t - 1; if (ls < 0) ls += L0; if (ls >= L0) ls -= L0;
        sx[t][c] = x[((size_t)b*L0 + ls)*CIN + c];
    }
    __syncthreads();
    float acc = 0.f;
    const float* wd = w + d*CIN*3;
#pragma unroll
    for (int c = 0; c < CIN; c++)
#pragma unroll
        for (int t = 0; t < 3; t++)
            acc += sx[t][c] * wd[c*3 + t];
    int i2 = d & ~1;
    float freq = expf((float)i2 * (-9.210340371976184f / 512.0f));
    float ang = (float)l * freq;
    float pe = (d & 1) ? cosf(ang) : sinf(ang);
    h[((size_t)b*L0 + l)*DM + d] = acc + pe;
}

// ---------------- tf32 tensor-core GEMM: C = act(A[M,K] @ W[N,K]^T + bias)(+R) ----------------
#define TBM 128
#define TBN 128
#define TBK 16
#define SPAD 4   // row stride TBK+4 = 20 floats -> conflict-free frag loads

__device__ __forceinline__ float cvt_tf32(float x)
{
    asm("cvt.rna.tf32.f32 %0, %0;" : "+f"(x));
    return x;
}

__device__ __forceinline__ void mma8(float* d, const uint32_t* a, const uint32_t* b)
{
    asm volatile(
        "mma.sync.aligned.m16n8k8.row.col.f32.tf32.tf32.f32 "
        "{%0,%1,%2,%3},{%4,%5,%6,%7},{%8,%9},{%0,%1,%2,%3};"
        : "+f"(d[0]), "+f"(d[1]), "+f"(d[2]), "+f"(d[3])
        : "r"(a[0]), "r"(a[1]), "r"(a[2]), "r"(a[3]), "r"(b[0]), "r"(b[1]));
}

// MODE: 0 plain+bias, 1 bias+gelu(exact), 2 bias+residual
template<int MODE>
__global__ __launch_bounds__(256) void gemm_tc(
    const float* __restrict__ A, const float* __restrict__ W,
    const float* __restrict__ bias, const float* __restrict__ R,
    float* __restrict__ C, int M, int N, int K)
{
    __shared__ __align__(16) float As[TBM][TBK + SPAD];
    __shared__ __align__(16) float Ws[TBN][TBK + SPAD];
    int tid = threadIdx.x;
    int wid = tid >> 5, lane = tid & 31;
    int m0 = blockIdx.y * TBM, n0 = blockIdx.x * TBN;
    int wm = (wid >> 2) * 64;      // warp m offset: 0 / 64
    int wn = (wid & 3) * 32;       // warp n offset: 0/32/64/96
    int lrow = tid >> 2;           // 0..63
    int lcol = (tid & 3) * 4;      // 0,4,8,12
    int qr = lane >> 2;            // 0..7
    int rt = lane & 3;             // 0..3
    float acc[4][4][4] = {};

    for (int k0 = 0; k0 < K; k0 += TBK) {
        float4 a0 = *(const float4*)&A[(size_t)(m0 + lrow)*K + k0 + lcol];
        float4 a1 = *(const float4*)&A[(size_t)(m0 + lrow + 64)*K + k0 + lcol];
        float4 w0 = *(const float4*)&W[(size_t)(n0 + lrow)*K + k0 + lcol];
        float4 w1 = *(const float4*)&W[(size_t)(n0 + lrow + 64)*K + k0 + lcol];
        a0.x = cvt_tf32(a0.x); a0.y = cvt_tf32(a0.y); a0.z = cvt_tf32(a0.z); a0.w = cvt_tf32(a0.w);
        a1.x = cvt_tf32(a1.x); a1.y = cvt_tf32(a1.y); a1.z = cvt_tf32(a1.z); a1.w = cvt_tf32(a1.w);
        w0.x = cvt_tf32(w0.x); w0.y = cvt_tf32(w0.y); w0.z = cvt_tf32(w0.z); w0.w = cvt_tf32(w0.w);
        w1.x = cvt_tf32(w1.x); w1.y = cvt_tf32(w1.y); w1.z = cvt_tf32(w1.z); w1.w = cvt_tf32(w1.w);
        *(float4*)&As[lrow][lcol]      = a0;
        *(float4*)&As[lrow + 64][lcol] = a1;
        *(float4*)&Ws[lrow][lcol]      = w0;
        *(float4*)&Ws[lrow + 64][lcol] = w1;
        __syncthreads();
#pragma unroll
        for (int ks = 0; ks < 2; ks++) {
            int kb = ks * 8;
            uint32_t af[4][4], bf[4][2];
#pragma unroll
            for (int mi = 0; mi < 4; mi++) {
                int r = wm + mi*16 + qr;
                af[mi][0] = __float_as_uint(As[r    ][kb + rt    ]);
                af[mi][1] = __float_as_uint(As[r + 8][kb + rt    ]);
                af[mi][2] = __float_as_uint(As[r    ][kb + rt + 4]);
                af[mi][3] = __float_as_uint(As[r + 8][kb + rt + 4]);
            }
#pragma unroll
            for (int ni = 0; ni < 4; ni++) {
                int c = wn + ni*8 + qr;
                bf[ni][0] = __float_as_uint(Ws[c][kb + rt    ]);
                bf[ni][1] = __float_as_uint(Ws[c][kb + rt + 4]);
            }
#pragma unroll
            for (int mi = 0; mi < 4; mi++)
#pragma unroll
                for (int ni = 0; ni < 4; ni++)
                    mma8(acc[mi][ni], af[mi], bf[ni]);
        }
        __syncthreads();
    }

    // epilogue: c0:(r,c) c1:(r,c+1) c2:(r+8,c) c3:(r+8,c+1), c = 2*rt
#pragma unroll
    for (int mi = 0; mi < 4; mi++) {
        int r = m0 + wm + mi*16 + qr;
#pragma unroll
        for (int ni = 0; ni < 4; ni++) {
            int c = n0 + wn + ni*8 + rt*2;
            float b0 = bias[c], b1 = bias[c+1];
#pragma unroll
            for (int half = 0; half < 2; half++) {
                int rr = r + half*8;
                float v0 = acc[mi][ni][half*2+0] + b0;
                float v1 = acc[mi][ni][half*2+1] + b1;
                if (MODE == 1) {
                    v0 = 0.5f * v0 * (1.0f + erff(v0 * 0.7071067811865475f));
                    v1 = 0.5f * v1 * (1.0f + erff(v1 * 0.7071067811865475f));
                }
                if (MODE == 2) {
                    v0 += R[(size_t)rr*N + c];
                    v1 += R[(size_t)rr*N + c + 1];
                }
                *(float2*)&C[(size_t)rr*N + c] = make_float2(v0, v1);
            }
        }
    }
}

// ---------------- ProbSparse: sampled m = max - mean ----------------
__global__ void sample_m_k(const float* __restrict__ Q, const float* __restrict__ Km,
                           const int* __restrict__ idx, float* __restrict__ Mout,
                           int L, int U)
{
    int b = blockIdx.z, h = blockIdx.y;
    int w = threadIdx.x >> 5, lane = threadIdx.x & 31;
    int l = blockIdx.x * 8 + w;
    float2 q2 = *(const float2*)(Q + ((size_t)b*L + l)*DM + h*DH + 2*lane);
    float mx = -INFINITY, sm = 0.f;
    const int* ip = idx + (size_t)l * U;
    for (int j = 0; j < U; j++) {
        int r = ip[j];
        float2 k2 = *(const float2*)(Km + ((size_t)b*L + r)*DM + h*DH + 2*lane);
        float p = q2.x*k2.x + q2.y*k2.y;
#pragma unroll
        for (int o = 16; o > 0; o >>= 1) p += __shfl_xor_sync(0xffffffffu, p, o);
        mx = fmaxf(mx, p); sm += p;
    }
    if (lane == 0) Mout[((size_t)b*NH + h)*L + l] = mx - sm / (float)U;
}

// ---------------- iterative top-u per (b,h) ----------------
__global__ void topk_k(const float* __restrict__ Min, int* __restrict__ top, int L, int U)
{
    __shared__ float sv[2048];
    __shared__ float rv[256];
    __shared__ int   ri[256];
    int bh = blockIdx.x, tid = threadIdx.x;
    const float* mp = Min + (size_t)bh * L;
    for (int i = tid; i < L; i += 256) sv[i] = mp[i];
    __syncthreads();
    for (int t = 0; t < U; t++) {
        float bv = -INFINITY; int bi = 0x7fffffff;
        for (int i = tid; i < L; i += 256) {
            float v = sv[i];
            if (v > bv || (v == bv && i < bi)) { bv = v; bi = i; }
        }
        rv[tid] = bv; ri[tid] = bi;
        __syncthreads();
        for (int s = 128; s > 0; s >>= 1) {
            if (tid < s) {
                if (rv[tid+s] > rv[tid] || (rv[tid+s] == rv[tid] && ri[tid+s] < ri[tid])) {
                    rv[tid] = rv[tid+s]; ri[tid] = ri[tid+s];
                }
            }
            __syncthreads();
        }
        if (tid == 0) { top[(size_t)bh*U + t] = ri[0]; sv[ri[0]] = -INFINITY; }
        __syncthreads();
    }
}

// ---------------- mean of V over L per (b,h,d) ----------------
__global__ void vmean_k(const float* __restrict__ V, float* __restrict__ out, int L)
{
    int b = blockIdx.y, h = blockIdx.x;
    int tid = threadIdx.x;
    int d = tid & 63, g = tid >> 6;
    __shared__ float red[4][64];
    float s = 0.f;
    for (int l = g; l < L; l += 4)
        s += V[((size_t)b*L + l)*DM + h*DH + d];
    red[g][d] = s;
    __syncthreads();
    if (g == 0)
        out[((size_t)b*NH + h)*DH + d] = (red[0][d]+red[1][d]+red[2][d]+red[3][d]) / (float)L;
}

__global__ void fillctx_k(const float* __restrict__ vm, float* __restrict__ ctx, int L)
{
    size_t i = (size_t)blockIdx.x * 256 + threadIdx.x;
    int d = (int)(i & 511);
    size_t bl = i >> 9;
    int b = (int)(bl / (size_t)L);
    int h = d >> 6, dd = d & 63;
    ctx[i] = vm[((size_t)b*NH + h)*DH + dd];
}

// ---------------- full attention for the u selected queries ----------------
__global__ void attn_top_k(const float* __restrict__ Q, const float* __restrict__ Km,
                           const float* __restrict__ V, const int* __restrict__ top,
                           float* __restrict__ ctx, int L, int U)
{
    __shared__ float sc[2048];
    __shared__ float wred[8];
    __shared__ float r2[256];
    __shared__ float fred[4][64];
    __shared__ float s_max;
    int b = blockIdx.z, h = blockIdx.y, j = blockIdx.x;
    int tid = threadIdx.x, w = tid >> 5, lane = tid & 31;
    int t = top[((size_t)b*NH + h)*U + j];
    float2 q2 = *(const float2*)(Q + ((size_t)b*L + t)*DM + h*DH + 2*lane);
    float wmax = -INFINITY;
    for (int r = w; r < L; r += 8) {
        float2 k2 = *(const float2*)(Km + ((size_t)b*L + r)*DM + h*DH + 2*lane);
        float p = q2.x*k2.x + q2.y*k2.y;
#pragma unroll
        for (int o = 16; o > 0; o >>= 1) p += __shfl_xor_sync(0xffffffffu, p, o);
        p *= 0.125f;
        if (lane == 0) sc[r] = p;
        wmax = fmaxf(wmax, p);
    }
    if (lane == 0) wred[w] = wmax;
    __syncthreads();
    if (tid == 0) {
        float mm = wred[0];
        for (int i2 = 1; i2 < 8; i2++) mm = fmaxf(mm, wred[i2]);
        s_max = mm;
    }
    __syncthreads();
    float mxv = s_max, ls = 0.f;
    for (int r = tid; r < L; r += 256) { float e = expf(sc[r] - mxv); sc[r] = e; ls += e; }
    r2[tid] = ls;
    __syncthreads();
    for (int s = 128; s > 0; s >>= 1) { if (tid < s) r2[tid] += r2[tid+s]; __syncthreads(); }
    float inv = 1.0f / r2[0];
    int d = tid & 63, g = tid >> 6;
    float acc = 0.f;
    for (int r = g; r < L; r += 4)
        acc += sc[r] * V[((size_t)b*L + r)*DM + h*DH + d];
    fred[g][d] = acc;
    __syncthreads();
    if (g == 0)
        ctx[((size_t)b*L + t)*DM + h*DH + d] =
            (fred[0][d] + fred[1][d] + fred[2][d] + fred[3][d]) * inv;
}

// ---------------- LayerNorm ----------------
__global__ void ln_k(const float* __restrict__ in, const float* __restrict__ g,
                     const float* __restrict__ be, float* __restrict__ out)
{
    __shared__ float red[512];
    __shared__ float s_mu, s_rstd;
    int d = threadIdx.x; size_t row = blockIdx.x;
    float v = in[row*DM + d];
    red[d] = v; __syncthreads();
    for (int s = 256; s > 0; s >>= 1) { if (d < s) red[d] += red[d+s]; __syncthreads(); }
    if (d == 0) s_mu = red[0] * (1.0f/512.0f);
    __syncthreads();
    float w = v - s_mu;
    red[d] = w*w; __syncthreads();
    for (int s = 256; s > 0; s >>= 1) { if (d < s) red[d] += red[d+s]; __syncthreads(); }
    if (d == 0) s_rstd = rsqrtf(red[0] * (1.0f/512.0f) + 1e-5f);
    __syncthreads();
    out[row*DM + d] = w * s_rstd * g[d] + be[d];
}

// ---------------- im2col for circular distilling conv ----------------
__global__ void im2col_k(const float* __restrict__ h, float* __restrict__ A2, int L)
{
    size_t i = (size_t)blockIdx.x * 256 + threadIdx.x;
    if (i >= (size_t)BATCH * L * 1536) return;
    int j = (int)(i % 1536);
    size_t bl = i / 1536;
    int b = (int)(bl / (size_t)L), l = (int)(bl % (size_t)L);
    int c = j / 3, t = j % 3;
    int ls = l + t - 1; if (ls < 0) ls += L; if (ls >= L) ls -= L;
    A2[i] = h[((size_t)b*L + ls)*DM + c];
}

// ---------------- BatchNorm stats ----------------
__global__ void bnstat1_k(const float* __restrict__ y, float* __restrict__ st, int M)
{
    int d = threadIdx.x, chunk = blockIdx.x;
    int rows = M / 64;
    const float* p = y + (size_t)chunk * rows * DM;
    float s = 0.f, s2 = 0.f;
    for (int r = 0; r < rows; r++) { float v = p[(size_t)r*DM + d]; s += v; s2 += v*v; }
    st[chunk*DM + d] = s;
    st[64*DM + chunk*DM + d] = s2;
}

__global__ void bnstat2_k(const float* __restrict__ st, const float* __restrict__ g,
                          const float* __restrict__ be, float* __restrict__ sc,
                          float* __restrict__ sh, int M)
{
    int d = threadIdx.x;
    float s = 0.f, s2 = 0.f;
    for (int c = 0; c < 64; c++) { s += st[c*DM + d]; s2 += st[64*DM + c*DM + d]; }
    float mu = s / (float)M;
    float var = s2 / (float)M - mu*mu;
    float scale = g[d] * rsqrtf(var + 1e-5f);
    sc[d] = scale; sh[d] = be[d] - mu*scale;
}

// ---------------- BN + ELU + maxpool ----------------
__global__ void pool_k(const float* __restrict__ y, const float* __restrict__ sc,
                       const float* __restrict__ sh, float* __restrict__ out, int L)
{
    int d = threadIdx.x, j = blockIdx.x, b = blockIdx.y;
    int Lh = L / 2;
    float scl = sc[d], shf = sh[d];
    float m = -INFINITY;
#pragma unroll
    for (int t = 0; t < 3; t++) {
        int ly = 2*j - 1 + t;
        if (ly < 0 || ly >= L) continue;
        float v = y[((size_t)b*L + ly)*DM + d] * scl + shf;
        v = v > 0.f ? v : expm1f(v);
        m = fmaxf(m, v);
    }
    out[((size_t)b*Lh + j)*DM + d] = m;
}

// ---------------- final LN(row L-1) @ proj + skip ----------------
__global__ void final_k(const float* __restrict__ h, const float* __restrict__ g,
                        const float* __restrict__ be, const float* __restrict__ pw,
                        const float* __restrict__ pb, const float* __restrict__ x,
                        const float* __restrict__ sw, const float* __restrict__ sb,
                        float* __restrict__ out, int L)
{
    __shared__ float red[512];
    __shared__ float sval[512];
    __shared__ float s_mu, s_rstd;
    int d = threadIdx.x, b = blockIdx.x;
    float v = h[((size_t)b*L + (L-1))*DM + d];
    red[d] = v; __syncthreads();
    for (int s = 256; s > 0; s >>= 1) { if (d < s) red[d] += red[d+s]; __syncthreads(); }
    if (d == 0) s_mu = red[0] * (1.0f/512.0f);
    __syncthreads();
    float w = v - s_mu;
    red[d] = w*w; __syncthreads();
    for (int s = 256; s > 0; s >>= 1) { if (d < s) red[d] += red[d+s]; __syncthreads(); }
    if (d == 0) s_rstd = rsqrtf(red[0] * (1.0f/512.0f) + 1e-5f);
    __syncthreads();
    sval[d] = w * s_rstd * g[d] + be[d];
    __syncthreads();
    if (d < POUT) {
        float acc = pb[d];
        for (int kk = 0; kk < 512; kk++) acc += sval[kk] * pw[d*512 + kk];
        float sk = sb[d];
        for (int cc = 0; cc < CIN; cc++)
            sk += x[((size_t)b*L0 + (L0-1))*CIN + cc] * sw[d*CIN + cc];
        out[b*POUT + d] = acc + sk;
    }
}

extern "C" void kernel_launch(void* const* d_in, const int* in_sizes, int n_in,
                              void* d_out, int out_size)
{
    (void)in_sizes; (void)n_in; (void)out_size;
    const float* x       = (const float*)d_in[0];
    const float* skip_w  = (const float*)d_in[1];
    const float* skip_b  = (const float*)d_in[2];
    const float* tconv_w = (const float*)d_in[3];
    const float* wq = (const float*)d_in[4];  const float* bq = (const float*)d_in[5];
    const float* wk = (const float*)d_in[6];  const float* bk = (const float*)d_in[7];
    const float* wv = (const float*)d_in[8];  const float* bv = (const float*)d_in[9];
    const float* wo = (const float*)d_in[10]; const float* bo = (const float*)d_in[11];
    const float* w1 = (const float*)d_in[12]; const float* b1 = (const float*)d_in[13];
    const float* w2 = (const float*)d_in[14]; const float* b2 = (const float*)d_in[15];
    const float* ln1_g = (const float*)d_in[16]; const float* ln1_b = (const float*)d_in[17];
    const float* ln2_g = (const float*)d_in[18]; const float* ln2_b = (const float*)d_in[19];
    const float* dc_w = (const float*)d_in[20]; const float* dc_b = (const float*)d_in[21];
    const float* bn_g = (const float*)d_in[22]; const float* bn_b = (const float*)d_in[23];
    const float* fln_g = (const float*)d_in[24]; const float* fln_b = (const float*)d_in[25];
    const float* proj_w = (const float*)d_in[26]; const float* proj_b = (const float*)d_in[27];
    float* out = (float*)d_out;

    float *h, *q, *k, *v, *c, *f, *m, *vm, *stats, *bnsc, *bnsh;
    int *idx, *topI;
    cudaGetSymbolAddress((void**)&h, g_h);
    cudaGetSymbolAddress((void**)&q, g_q);
    cudaGetSymbolAddress((void**)&k, g_k);
    cudaGetSymbolAddress((void**)&v, g_v);
    cudaGetSymbolAddress((void**)&c, g_c);
    cudaGetSymbolAddress((void**)&f, g_f);
    cudaGetSymbolAddress((void**)&m, g_m);
    cudaGetSymbolAddress((void**)&vm, g_vmean);
    cudaGetSymbolAddress((void**)&stats, g_stats);
    cudaGetSymbolAddress((void**)&bnsc, g_bnsc);
    cudaGetSymbolAddress((void**)&bnsh, g_bnsh);
    cudaGetSymbolAddress((void**)&idx, g_idx);
    cudaGetSymbolAddress((void**)&topI, g_top);

    tokconv_k<<<dim3(L0, BATCH), DM>>>(x, tconv_w, h);

    int L = L0;
    const int Uarr[3] = {38, 34, 31};
    int idx_off = 0;
    for (int i = 0; i < 3; i++) {
        int U = Uarr[i];
        int M = BATCH * L;
        unsigned fk0, fk1, s2a, s2b;
        tf2x32(0u, 42u, 0u, (unsigned)i, fk0, fk1);
        tf2x32(fk0, fk1, 0u, 1u, s2a, s2b);
        int n = L * U;
        idx_k<<<(n + 255)/256, 256>>>(s2a, s2b, n, (unsigned)(L - 1), idx + idx_off);

        // Q, K, V projections (tf32 tensor core)
        gemm_tc<0><<<dim3(DM/TBN, M/TBM), 256>>>(h, wq + (size_t)i*DM*DM, bq + i*DM, nullptr, q, M, DM, DM);
        gemm_tc<0><<<dim3(DM/TBN, M/TBM), 256>>>(h, wk + (size_t)i*DM*DM, bk + i*DM, nullptr, k, M, DM, DM);
        gemm_tc<0><<<dim3(DM/TBN, M/TBM), 256>>>(h, wv + (size_t)i*DM*DM, bv + i*DM, nullptr, v, M, DM, DM);

        // ProbSparse attention
        sample_m_k<<<dim3(L/8, NH, BATCH), 256>>>(q, k, idx + idx_off, m, L, U);
        topk_k<<<BATCH*NH, 256>>>(m, topI, L, U);
        vmean_k<<<dim3(NH, BATCH), 256>>>(v, vm, L);
        fillctx_k<<<(unsigned)(((size_t)M*DM)/256), 256>>>(vm, c, L);
        attn_top_k<<<dim3(U, NH, BATCH), 256>>>(q, k, v, topI, c, L, U);

        // WO projection + residual
        gemm_tc<2><<<dim3(DM/TBN, M/TBM), 256>>>(c, wo + (size_t)i*DM*DM, bo + i*DM, h, h, M, DM, DM);

        // FFN
        ln_k<<<M, DM>>>(h, ln1_g + i*DM, ln1_b + i*DM, c);
        gemm_tc<1><<<dim3(DFF_/TBN, M/TBM), 256>>>(c, w1 + (size_t)i*DFF_*DM, b1 + i*DFF_, nullptr, f, M, DFF_, DM);
        gemm_tc<2><<<dim3(DM/TBN, M/TBM), 256>>>(f, w2 + (size_t)i*DM*DFF_, b2 + i*DM, h, c, M, DM, DFF_);
        ln_k<<<M, DM>>>(c, ln2_g + i*DM, ln2_b + i*DM, h);

        // distilling conv layer
        if (i < 2) {
            im2col_k<<<(unsigned)(((size_t)M*1536 + 255)/256), 256>>>(h, f, L);
            gemm_tc<0><<<dim3(DM/TBN, M/TBM), 256>>>(f, dc_w + (size_t)i*DM*1536, dc_b + i*DM, nullptr, c, M, DM, 1536);
            bnstat1_k<<<64, DM>>>(c, stats, M);
            bnstat2_k<<<1, DM>>>(stats, bn_g + i*DM, bn_b + i*DM, bnsc, bnsh, M);
            pool_k<<<dim3(L/2, BATCH), DM>>>(c, bnsc, bnsh, h, L);
            L /= 2;
        }
        idx_off += n;
    }

    final_k<<<BATCH, DM>>>(h, fln_g, fln_b, proj_w, proj_b, x, skip_w, skip_b, out, L);
}

// round 5
// speedup vs baseline: 2.9220x; 1.2077x over previous
#include <cuda_runtime.h>
#include <cuda_bf16.h>
#include <math.h>
#include <stdint.h>

#define BATCH 32
#define L0    2048
#define CIN   7
#define DM    512
#define DFF_  2048
#define NH    8
#define DH    64
#define POUT  96

// ---------------- scratch ----------------
__device__ __align__(128) float g_h[(size_t)BATCH*L0*DM];
__device__ __align__(128) float g_q[(size_t)BATCH*L0*DM];
__device__ __align__(128) float g_k[(size_t)BATCH*L0*DM];
__device__ __align__(128) float g_v[(size_t)BATCH*L0*DM];
__device__ __align__(128) float g_c[(size_t)BATCH*L0*DM];
__device__ __align__(128) float g_f[(size_t)BATCH*L0*DFF_];
__device__ __align__(128) float g_m[(size_t)BATCH*NH*L0];
__device__ __align__(128) int   g_top[BATCH*NH*64];
__device__ __align__(128) float g_vmean[BATCH*NH*DH];
__device__ __align__(128) int   g_idx[L0*38 + 1024*34 + 512*31];
__device__ __align__(128) float g_stats[2*64*DM];
__device__ __align__(128) float g_bnsc[DM];
__device__ __align__(128) float g_bnsh[DM];
__device__ __align__(128) float g_wr[DM*1536];

// ---------------- threefry2x32 ----------------
__host__ __device__ inline void tf2x32(unsigned k0, unsigned k1, unsigned c0, unsigned c1,
                                       unsigned& o0, unsigned& o1)
{
    unsigned ks0 = k0, ks1 = k1, ks2 = k0 ^ k1 ^ 0x1BD11BDAu;
    unsigned x0 = c0 + ks0, x1 = c1 + ks1;
#define TFR(r) { x0 += x1; x1 = (x1 << (r)) | (x1 >> (32 - (r))); x1 ^= x0; }
    TFR(13) TFR(15) TFR(26) TFR(6)   x0 += ks1; x1 += ks2 + 1u;
    TFR(17) TFR(29) TFR(16) TFR(24)  x0 += ks2; x1 += ks0 + 2u;
    TFR(13) TFR(15) TFR(26) TFR(6)   x0 += ks0; x1 += ks1 + 3u;
    TFR(17) TFR(29) TFR(16) TFR(24)  x0 += ks1; x1 += ks2 + 4u;
    TFR(13) TFR(15) TFR(26) TFR(6)   x0 += ks2; x1 += ks0 + 5u;
#undef TFR
    o0 = x0; o1 = x1;
}

__global__ void idx_k(unsigned ka, unsigned kb, int n, unsigned mask, int* __restrict__ out)
{
    int i = blockIdx.x * 256 + threadIdx.x;
    if (i >= n) return;
    unsigned v0, v1;
    tf2x32(ka, kb, 0u, (unsigned)i, v0, v1);
    out[i] = (int)((v0 ^ v1) & mask);
}

// ---------------- token conv + positional embedding ----------------
__global__ void tokconv_k(const float* __restrict__ x, const float* __restrict__ w,
                          float* __restrict__ h)
{
    int l = blockIdx.x, b = blockIdx.y;
    int d = threadIdx.x;
    __shared__ float sx[3][CIN];
    if (threadIdx.x < 21) {
        int t = threadIdx.x / 7, c = threadIdx.x % 7;
        int ls = l + t - 1; if (ls < 0) ls += L0; if (ls >= L0) ls -= L0;
        sx[t][c] = x[((size_t)b*L0 + ls)*CIN + c];
    }
    __syncthreads();
    float acc = 0.f;
    const float* wd = w + d*CIN*3;
#pragma unroll
    for (int c = 0; c < CIN; c++)
#pragma unroll
        for (int t = 0; t < 3; t++)
            acc += sx[t][c] * wd[c*3 + t];
    int i2 = d & ~1;
    float freq = expf((float)i2 * (-9.210340371976184f / 512.0f));
    float ang = (float)l * freq;
    float pe = (d & 1) ? cosf(ang) : sinf(ang);
    h[((size_t)b*L0 + l)*DM + d] = acc + pe;
}

// ---------------- cp.async helpers ----------------
__device__ __forceinline__ void cp16(void* smem, const void* gptr)
{
    unsigned s = (unsigned)__cvta_generic_to_shared(smem);
    asm volatile("cp.async.cg.shared.global [%0], [%1], 16;\n" :: "r"(s), "l"(gptr));
}
__device__ __forceinline__ void cp_commit() { asm volatile("cp.async.commit_group;\n"); }
__device__ __forceinline__ void cp_wait1()  { asm volatile("cp.async.wait_group 1;\n"); }
__device__ __forceinline__ void cp_wait0()  { asm volatile("cp.async.wait_group 0;\n"); }

__device__ __forceinline__ uint32_t ldcvt(float v)
{
    asm("cvt.rna.tf32.f32 %0, %0;" : "+f"(v));
    return __float_as_uint(v);
}

__device__ __forceinline__ void mma8(float* d, const uint32_t* a, const uint32_t* b)
{
    asm volatile(
        "mma.sync.aligned.m16n8k8.row.col.f32.tf32.tf32.f32 "
        "{%0,%1,%2,%3},{%4,%5,%6,%7},{%8,%9},{%0,%1,%2,%3};"
        : "+f"(d[0]), "+f"(d[1]), "+f"(d[2]), "+f"(d[3])
        : "r"(a[0]), "r"(a[1]), "r"(a[2]), "r"(a[3]), "r"(b[0]), "r"(b[1]));
}

#define TBM 128
#define TBN 128
#define TBK 16
#define SPAD 4

// ---------------- tf32 GEMM, cp.async double-buffered ----------------
// MODE: 0 plain+bias, 1 bias+gelu(exact), 2 bias+residual
template<int MODE>
__global__ __launch_bounds__(256) void gemm_tc(
    const float* __restrict__ A, const float* __restrict__ W,
    const float* __restrict__ bias, const float* __restrict__ R,
    float* __restrict__ C, int M, int N, int K)
{
    __shared__ __align__(16) float As[2][TBM][TBK + SPAD];
    __shared__ __align__(16) float Ws[2][TBN][TBK + SPAD];
    int tid = threadIdx.x;
    int wid = tid >> 5, lane = tid & 31;
    int m0 = blockIdx.y * TBM, n0 = blockIdx.x * TBN;
    int wm = (wid >> 2) * 64, wn = (wid & 3) * 32;
    int lrow = tid >> 2, lcol = (tid & 3) * 4;
    int qr = lane >> 2, rt = lane & 3;
    float acc[4][4][4] = {};
    const float* Ap = A + (size_t)(m0 + lrow)*K + lcol;
    const float* Wp = W + (size_t)(n0 + lrow)*K + lcol;
    int T = K / TBK;

    cp16(&As[0][lrow][lcol],      Ap);
    cp16(&As[0][lrow + 64][lcol], Ap + (size_t)64*K);
    cp16(&Ws[0][lrow][lcol],      Wp);
    cp16(&Ws[0][lrow + 64][lcol], Wp + (size_t)64*K);
    cp_commit();

    for (int t = 0; t < T; t++) {
        if (t + 1 < T) {
            int s = (t + 1) & 1;
            const float* Ap2 = Ap + (size_t)(t + 1)*TBK;
            const float* Wp2 = Wp + (size_t)(t + 1)*TBK;
            cp16(&As[s][lrow][lcol],      Ap2);
            cp16(&As[s][lrow + 64][lcol], Ap2 + (size_t)64*K);
            cp16(&Ws[s][lrow][lcol],      Wp2);
            cp16(&Ws[s][lrow + 64][lcol], Wp2 + (size_t)64*K);
            cp_commit();
            cp_wait1();
        } else {
            cp_wait0();
        }
        __syncthreads();
        int s = t & 1;
#pragma unroll
        for (int ks = 0; ks < 2; ks++) {
            int kb = ks * 8;
            uint32_t af[4][4], bf[4][2];
#pragma unroll
            for (int mi = 0; mi < 4; mi++) {
                int r = wm + mi*16 + qr;
                af[mi][0] = ldcvt(As[s][r    ][kb + rt    ]);
                af[mi][1] = ldcvt(As[s][r + 8][kb + rt    ]);
                af[mi][2] = ldcvt(As[s][r    ][kb + rt + 4]);
                af[mi][3] = ldcvt(As[s][r + 8][kb + rt + 4]);
            }
#pragma unroll
            for (int ni = 0; ni < 4; ni++) {
                int c = wn + ni*8 + qr;
                bf[ni][0] = ldcvt(Ws[s][c][kb + rt    ]);
                bf[ni][1] = ldcvt(Ws[s][c][kb + rt + 4]);
            }
#pragma unroll
            for (int mi = 0; mi < 4; mi++)
#pragma unroll
                for (int ni = 0; ni < 4; ni++)
                    mma8(acc[mi][ni], af[mi], bf[ni]);
        }
        __syncthreads();
    }

#pragma unroll
    for (int mi = 0; mi < 4; mi++) {
        int r = m0 + wm + mi*16 + qr;
#pragma unroll
        for (int ni = 0; ni < 4; ni++) {
            int c = n0 + wn + ni*8 + rt*2;
            float b0 = bias[c], b1 = bias[c+1];
#pragma unroll
            for (int half = 0; half < 2; half++) {
                int rr = r + half*8;
                float v0 = acc[mi][ni][half*2+0] + b0;
                float v1 = acc[mi][ni][half*2+1] + b1;
                if (MODE == 1) {
                    v0 = 0.5f * v0 * (1.0f + erff(v0 * 0.7071067811865475f));
                    v1 = 0.5f * v1 * (1.0f + erff(v1 * 0.7071067811865475f));
                }
                if (MODE == 2) {
                    v0 += R[(size_t)rr*N + c];
                    v1 += R[(size_t)rr*N + c + 1];
                }
                *(float2*)&C[(size_t)rr*N + c] = make_float2(v0, v1);
            }
        }
    }
}

// ---------------- distilling conv weight reorder: wr[n][t*512+c] = w[n][c*3+t] ----------------
__global__ void wreorder_k(const float* __restrict__ w, float* __restrict__ wr)
{
    int n = blockIdx.x, c = threadIdx.x;
#pragma unroll
    for (int t = 0; t < 3; t++)
        wr[(size_t)n*1536 + t*512 + c] = w[(size_t)n*1536 + c*3 + t];
}

// ---------------- direct circular-conv GEMM (A read from h, K=1536) ----------------
__global__ __launch_bounds__(256) void gemm_conv(
    const float* __restrict__ Hsrc, const float* __restrict__ W,
    const float* __restrict__ bias, float* __restrict__ C,
    int lshift, int Lmask)
{
    const int K = 1536, N = DM;
    __shared__ __align__(16) float As[2][TBM][TBK + SPAD];
    __shared__ __align__(16) float Ws[2][TBN][TBK + SPAD];
    int tid = threadIdx.x;
    int wid = tid >> 5, lane = tid & 31;
    int m0 = blockIdx.y * TBM, n0 = blockIdx.x * TBN;
    int wm = (wid >> 2) * 64, wn = (wid & 3) * 32;
    int lrow = tid >> 2, lcol = (tid & 3) * 4;
    int qr = lane >> 2, rt = lane & 3;
    float acc[4][4][4] = {};
    int m1 = m0 + lrow, m2 = m0 + lrow + 64;
    int b1 = m1 >> lshift, l1 = m1 & Lmask;
    int b2 = m2 >> lshift, l2 = m2 & Lmask;
    const float* Wp = W + (size_t)(n0 + lrow)*K + lcol;
    int T = K / TBK;   // 96

    // issue for tile t into stage s
    auto issueA = [&](int t, int s) {
        int kt = t * TBK;
        int tt = kt >> 9;             // tap 0..2
        int cc = (kt & 511) + lcol;   // channel
        int ls1 = (l1 + tt - 1 + (Lmask+1)) & Lmask;
        int ls2 = (l2 + tt - 1 + (Lmask+1)) & Lmask;
        cp16(&As[s][lrow][lcol],      Hsrc + ((size_t)(b1 << lshift) + ls1)*DM + cc);
        cp16(&As[s][lrow + 64][lcol], Hsrc + ((size_t)(b2 << lshift) + ls2)*DM + cc);
        cp16(&Ws[s][lrow][lcol],      Wp + (size_t)t*TBK);
        cp16(&Ws[s][lrow + 64][lcol], Wp + (size_t)t*TBK + (size_t)64*K);
        cp_commit();
    };

    issueA(0, 0);
    for (int t = 0; t < T; t++) {
        if (t + 1 < T) { issueA(t + 1, (t + 1) & 1); cp_wait1(); }
        else           { cp_wait0(); }
        __syncthreads();
        int s = t & 1;
#pragma unroll
        for (int ks = 0; ks < 2; ks++) {
            int kb = ks * 8;
            uint32_t af[4][4], bf[4][2];
#pragma unroll
            for (int mi = 0; mi < 4; mi++) {
                int r = wm + mi*16 + qr;
                af[mi][0] = ldcvt(As[s][r    ][kb + rt    ]);
                af[mi][1] = ldcvt(As[s][r + 8][kb + rt    ]);
                af[mi][2] = ldcvt(As[s][r    ][kb + rt + 4]);
                af[mi][3] = ldcvt(As[s][r + 8][kb + rt + 4]);
            }
#pragma unroll
            for (int ni = 0; ni < 4; ni++) {
                int c = wn + ni*8 + qr;
                bf[ni][0] = ldcvt(Ws[s][c][kb + rt    ]);
                bf[ni][1] = ldcvt(Ws[s][c][kb + rt + 4]);
            }
#pragma unroll
            for (int mi = 0; mi < 4; mi++)
#pragma unroll
                for (int ni = 0; ni < 4; ni++)
                    mma8(acc[mi][ni], af[mi], bf[ni]);
        }
        __syncthreads();
    }

#pragma unroll
    for (int mi = 0; mi < 4; mi++) {
        int r = m0 + wm + mi*16 + qr;
#pragma unroll
        for (int ni = 0; ni < 4; ni++) {
            int c = n0 + wn + ni*8 + rt*2;
            float b0 = bias[c], b1v = bias[c+1];
#pragma unroll
            for (int half = 0; half < 2; half++) {
                int rr = r + half*8;
                *(float2*)&C[(size_t)rr*N + c] =
                    make_float2(acc[mi][ni][half*2+0] + b0, acc[mi][ni][half*2+1] + b1v);
            }
        }
    }
}

// ---------------- ProbSparse: sampled m = max - mean ----------------
__global__ void sample_m_k(const float* __restrict__ Q, const float* __restrict__ Km,
                           const int* __restrict__ idx, float* __restrict__ Mout,
                           int L, int U)
{
    int b = blockIdx.z, h = blockIdx.y;
    int w = threadIdx.x >> 5, lane = threadIdx.x & 31;
    int l = blockIdx.x * 8 + w;
    float2 q2 = *(const float2*)(Q + ((size_t)b*L + l)*DM + h*DH + 2*lane);
    float mx = -INFINITY, sm = 0.f;
    const int* ip = idx + (size_t)l * U;
    for (int j = 0; j < U; j++) {
        int r = ip[j];
        float2 k2 = *(const float2*)(Km + ((size_t)b*L + r)*DM + h*DH + 2*lane);
        float p = q2.x*k2.x + q2.y*k2.y;
#pragma unroll
        for (int o = 16; o > 0; o >>= 1) p += __shfl_xor_sync(0xffffffffu, p, o);
        mx = fmaxf(mx, p); sm += p;
    }
    if (lane == 0) Mout[((size_t)b*NH + h)*L + l] = mx - sm / (float)U;
}

// ---------------- iterative top-u per (b,h) ----------------
__global__ void topk_k(const float* __restrict__ Min, int* __restrict__ top, int L, int U)
{
    __shared__ float sv[2048];
    __shared__ float rv[256];
    __shared__ int   ri[256];
    int bh = blockIdx.x, tid = threadIdx.x;
    const float* mp = Min + (size_t)bh * L;
    for (int i = tid; i < L; i += 256) sv[i] = mp[i];
    __syncthreads();
    for (int t = 0; t < U; t++) {
        float bv = -INFINITY; int bi = 0x7fffffff;
        for (int i = tid; i < L; i += 256) {
            float v = sv[i];
            if (v > bv || (v == bv && i < bi)) { bv = v; bi = i; }
        }
        rv[tid] = bv; ri[tid] = bi;
        __syncthreads();
        for (int s = 128; s > 0; s >>= 1) {
            if (tid < s) {
                if (rv[tid+s] > rv[tid] || (rv[tid+s] == rv[tid] && ri[tid+s] < ri[tid])) {
                    rv[tid] = rv[tid+s]; ri[tid] = ri[tid+s];
                }
            }
            __syncthreads();
        }
        if (tid == 0) { top[(size_t)bh*U + t] = ri[0]; sv[ri[0]] = -INFINITY; }
        __syncthreads();
    }
}

// ---------------- mean of V over L per (b,h,d) ----------------
__global__ void vmean_k(const float* __restrict__ V, float* __restrict__ out, int L)
{
    int b = blockIdx.y, h = blockIdx.x;
    int tid = threadIdx.x;
    int d = tid & 63, g = tid >> 6;
    __shared__ float red[4][64];
    float s = 0.f;
    for (int l = g; l < L; l += 4)
        s += V[((size_t)b*L + l)*DM + h*DH + d];
    red[g][d] = s;
    __syncthreads();
    if (g == 0)
        out[((size_t)b*NH + h)*DH + d] = (red[0][d]+red[1][d]+red[2][d]+red[3][d]) / (float)L;
}

__global__ void fillctx_k(const float* __restrict__ vm, float* __restrict__ ctx, int L)
{
    size_t i = (size_t)blockIdx.x * 256 + threadIdx.x;
    int d = (int)(i & 511);
    size_t bl = i >> 9;
    int b = (int)(bl / (size_t)L);
    int h = d >> 6, dd = d & 63;
    ctx[i] = vm[((size_t)b*NH + h)*DH + dd];
}

// ---------------- flash-style attention for top-u queries, one block per (b,h) ----------------
#define ATILE 64
__global__ __launch_bounds__(256) void attn_flash_k(
    const float* __restrict__ Q, const float* __restrict__ Km,
    const float* __restrict__ V, const int* __restrict__ top,
    float* __restrict__ ctx, int L, int U)
{
    __shared__ float Ks[ATILE][DH];
    __shared__ float Vs[ATILE][DH];
    int h = blockIdx.x, b = blockIdx.y;
    int tid = threadIdx.x, w = tid >> 5, lane = tid & 31;

    float2 qv[5]; int tq[5]; bool act[5];
    float mx[5], ss[5]; float2 acc[5];
#pragma unroll
    for (int i = 0; i < 5; i++) {
        int j = w + 8*i;
        act[i] = (j < U);
        int t = act[i] ? top[((size_t)b*NH + h)*U + j] : 0;
        tq[i] = t;
        qv[i] = *(const float2*)(Q + ((size_t)b*L + t)*DM + h*DH + 2*lane);
        mx[i] = -INFINITY; ss[i] = 0.f; acc[i] = make_float2(0.f, 0.f);
    }
    const float* Kb = Km + (size_t)b*L*DM + h*DH;
    const float* Vb = V  + (size_t)b*L*DM + h*DH;

    for (int r0 = 0; r0 < L; r0 += ATILE) {
        __syncthreads();
        for (int i = tid; i < ATILE*16; i += 256) {
            int r = i >> 4, c4 = (i & 15) * 4;
            *(float4*)&Ks[r][c4] = *(const float4*)(Kb + (size_t)(r0 + r)*DM + c4);
            *(float4*)&Vs[r][c4] = *(const float4*)(Vb + (size_t)(r0 + r)*DM + c4);
        }
        __syncthreads();
        for (int r = 0; r < ATILE; r++) {
            float2 kv = *(float2*)&Ks[r][2*lane];
            float2 vv = *(float2*)&Vs[r][2*lane];
#pragma unroll
            for (int i = 0; i < 5; i++) {
                float p = qv[i].x*kv.x + qv[i].y*kv.y;
                p += __shfl_xor_sync(0xffffffffu, p, 16);
                p += __shfl_xor_sync(0xffffffffu, p, 8);
                p += __shfl_xor_sync(0xffffffffu, p, 4);
                p += __shfl_xor_sync(0xffffffffu, p, 2);
                p += __shfl_xor_sync(0xffffffffu, p, 1);
                p *= 0.125f;
                float mn = fmaxf(mx[i], p);
                float corr = __expf(mx[i] - mn);
                float e = __expf(p - mn);
                ss[i] = ss[i]*corr + e;
                acc[i].x = acc[i].x*corr + e*vv.x;
                acc[i].y = acc[i].y*corr + e*vv.y;
                mx[i] = mn;
            }
        }
    }
#pragma unroll
    for (int i = 0; i < 5; i++) {
        if (!act[i]) continue;
        float inv = 1.0f / ss[i];
        *(float2*)(ctx + ((size_t)b*L + tq[i])*DM + h*DH + 2*lane) =
            make_float2(acc[i].x*inv, acc[i].y*inv);
    }
}

// ---------------- LayerNorm ----------------
__global__ void ln_k(const float* __restrict__ in, const float* __restrict__ g,
                     const float* __restrict__ be, float* __restrict__ out)
{
    __shared__ float red[512];
    __shared__ float s_mu, s_rstd;
    int d = threadIdx.x; size_t row = blockIdx.x;
    float v = in[row*DM + d];
    red[d] = v; __syncthreads();
    for (int s = 256; s > 0; s >>= 1) { if (d < s) red[d] += red[d+s]; __syncthreads(); }
    if (d == 0) s_mu = red[0] * (1.0f/512.0f);
    __syncthreads();
    float w = v - s_mu;
    red[d] = w*w; __syncthreads();
    for (int s = 256; s > 0; s >>= 1) { if (d < s) red[d] += red[d+s]; __syncthreads(); }
    if (d == 0) s_rstd = rsqrtf(red[0] * (1.0f/512.0f) + 1e-5f);
    __syncthreads();
    out[row*DM + d] = w * s_rstd * g[d] + be[d];
}

// ---------------- BatchNorm stats ----------------
__global__ void bnstat1_k(const float* __restrict__ y, float* __restrict__ st, int M)
{
    int d = threadIdx.x, chunk = blockIdx.x;
    int rows = M / 64;
    const float* p = y + (size_t)chunk * rows * DM;
    float s = 0.f, s2 = 0.f;
    for (int r = 0; r < rows; r++) { float v = p[(size_t)r*DM + d]; s += v; s2 += v*v; }
    st[chunk*DM + d] = s;
    st[64*DM + chunk*DM + d] = s2;
}

__global__ void bnstat2_k(const float* __restrict__ st, const float* __restrict__ g,
                          const float* __restrict__ be, float* __restrict__ sc,
                          float* __restrict__ sh, int M)
{
    int d = threadIdx.x;
    float s = 0.f, s2 = 0.f;
    for (int c = 0; c < 64; c++) { s += st[c*DM + d]; s2 += st[64*DM + c*DM + d]; }
    float mu = s / (float)M;
    float var = s2 / (float)M - mu*mu;
    float scale = g[d] * rsqrtf(var + 1e-5f);
    sc[d] = scale; sh[d] = be[d] - mu*scale;
}

// ---------------- BN + ELU + maxpool ----------------
__global__ void pool_k(const float* __restrict__ y, const float* __restrict__ sc,
                       const float* __restrict__ sh, float* __restrict__ out, int L)
{
    int d = threadIdx.x, j = blockIdx.x, b = blockIdx.y;
    int Lh = L / 2;
    float scl = sc[d], shf = sh[d];
    float m = -INFINITY;
#pragma unroll
    for (int t = 0; t < 3; t++) {
        int ly = 2*j - 1 + t;
        if (ly < 0 || ly >= L) continue;
        float v = y[((size_t)b*L + ly)*DM + d] * scl + shf;
        v = v > 0.f ? v : expm1f(v);
        m = fmaxf(m, v);
    }
    out[((size_t)b*Lh + j)*DM + d] = m;
}

// ---------------- final LN(row L-1) @ proj + skip ----------------
__global__ void final_k(const float* __restrict__ h, const float* __restrict__ g,
                        const float* __restrict__ be, const float* __restrict__ pw,
                        const float* __restrict__ pb, const float* __restrict__ x,
                        const float* __restrict__ sw, const float* __restrict__ sb,
                        float* __restrict__ out, int L)
{
    __shared__ float red[512];
    __shared__ float sval[512];
    __shared__ float s_mu, s_rstd;
    int d = threadIdx.x, b = blockIdx.x;
    float v = h[((size_t)b*L + (L-1))*DM + d];
    red[d] = v; __syncthreads();
    for (int s = 256; s > 0; s >>= 1) { if (d < s) red[d] += red[d+s]; __syncthreads(); }
    if (d == 0) s_mu = red[0] * (1.0f/512.0f);
    __syncthreads();
    float w = v - s_mu;
    red[d] = w*w; __syncthreads();
    for (int s = 256; s > 0; s >>= 1) { if (d < s) red[d] += red[d+s]; __syncthreads(); }
    if (d == 0) s_rstd = rsqrtf(red[0] * (1.0f/512.0f) + 1e-5f);
    __syncthreads();
    sval[d] = w * s_rstd * g[d] + be[d];
    __syncthreads();
    if (d < POUT) {
        float acc = pb[d];
        for (int kk = 0; kk < 512; kk++) acc += sval[kk] * pw[d*512 + kk];
        float sk = sb[d];
        for (int cc = 0; cc < CIN; cc++)
            sk += x[((size_t)b*L0 + (L0-1))*CIN + cc] * sw[d*CIN + cc];
        out[b*POUT + d] = acc + sk;
    }
}

extern "C" void kernel_launch(void* const* d_in, const int* in_sizes, int n_in,
                              void* d_out, int out_size)
{
    (void)in_sizes; (void)n_in; (void)out_size;
    const float* x       = (const float*)d_in[0];
    const float* skip_w  = (const float*)d_in[1];
    const float* skip_b  = (const float*)d_in[2];
    const float* tconv_w = (const float*)d_in[3];
    const float* wq = (const float*)d_in[4];  const float* bq = (const float*)d_in[5];
    const float* wk = (const float*)d_in[6];  const float* bk = (const float*)d_in[7];
    const float* wv = (const float*)d_in[8];  const float* bv = (const float*)d_in[9];
    const float* wo = (const float*)d_in[10]; const float* bo = (const float*)d_in[11];
    const float* w1 = (const float*)d_in[12]; const float* b1 = (const float*)d_in[13];
    const float* w2 = (const float*)d_in[14]; const float* b2 = (const float*)d_in[15];
    const float* ln1_g = (const float*)d_in[16]; const float* ln1_b = (const float*)d_in[17];
    const float* ln2_g = (const float*)d_in[18]; const float* ln2_b = (const float*)d_in[19];
    const float* dc_w = (const float*)d_in[20]; const float* dc_b = (const float*)d_in[21];
    const float* bn_g = (const float*)d_in[22]; const float* bn_b = (const float*)d_in[23];
    const float* fln_g = (const float*)d_in[24]; const float* fln_b = (const float*)d_in[25];
    const float* proj_w = (const float*)d_in[26]; const float* proj_b = (const float*)d_in[27];
    float* out = (float*)d_out;

    float *h, *q, *k, *v, *c, *f, *m, *vm, *stats, *bnsc, *bnsh, *wr;
    int *idx, *topI;
    cudaGetSymbolAddress((void**)&h, g_h);
    cudaGetSymbolAddress((void**)&q, g_q);
    cudaGetSymbolAddress((void**)&k, g_k);
    cudaGetSymbolAddress((void**)&v, g_v);
    cudaGetSymbolAddress((void**)&c, g_c);
    cudaGetSymbolAddress((void**)&f, g_f);
    cudaGetSymbolAddress((void**)&m, g_m);
    cudaGetSymbolAddress((void**)&vm, g_vmean);
    cudaGetSymbolAddress((void**)&stats, g_stats);
    cudaGetSymbolAddress((void**)&bnsc, g_bnsc);
    cudaGetSymbolAddress((void**)&bnsh, g_bnsh);
    cudaGetSymbolAddress((void**)&wr, g_wr);
    cudaGetSymbolAddress((void**)&idx, g_idx);
    cudaGetSymbolAddress((void**)&topI, g_top);

    tokconv_k<<<dim3(L0, BATCH), DM>>>(x, tconv_w, h);

    int L = L0;
    int lshift = 11;   // log2(2048)
    const int Uarr[3] = {38, 34, 31};
    int idx_off = 0;
    for (int i = 0; i < 3; i++) {
        int U = Uarr[i];
        int M = BATCH * L;
        unsigned fk0, fk1, s2a, s2b;
        tf2x32(0u, 42u, 0u, (unsigned)i, fk0, fk1);
        tf2x32(fk0, fk1, 0u, 1u, s2a, s2b);
        int n = L * U;
        idx_k<<<(n + 255)/256, 256>>>(s2a, s2b, n, (unsigned)(L - 1), idx + idx_off);

        gemm_tc<0><<<dim3(DM/TBN, M/TBM), 256>>>(h, wq + (size_t)i*DM*DM, bq + i*DM, nullptr, q, M, DM, DM);
        gemm_tc<0><<<dim3(DM/TBN, M/TBM), 256>>>(h, wk + (size_t)i*DM*DM, bk + i*DM, nullptr, k, M, DM, DM);
        gemm_tc<0><<<dim3(DM/TBN, M/TBM), 256>>>(h, wv + (size_t)i*DM*DM, bv + i*DM, nullptr, v, M, DM, DM);

        sample_m_k<<<dim3(L/8, NH, BATCH), 256>>>(q, k, idx + idx_off, m, L, U);
        topk_k<<<BATCH*NH, 256>>>(m, topI, L, U);
        vmean_k<<<dim3(NH, BATCH), 256>>>(v, vm, L);
        fillctx_k<<<(unsigned)(((size_t)M*DM)/256), 256>>>(vm, c, L);
        attn_flash_k<<<dim3(NH, BATCH), 256>>>(q, k, v, topI, c, L, U);

        gemm_tc<2><<<dim3(DM/TBN, M/TBM), 256>>>(c, wo + (size_t)i*DM*DM, bo + i*DM, h, h, M, DM, DM);

        ln_k<<<M, DM>>>(h, ln1_g + i*DM, ln1_b + i*DM, c);
        gemm_tc<1><<<dim3(DFF_/TBN, M/TBM), 256>>>(c, w1 + (size_t)i*DFF_*DM, b1 + i*DFF_, nullptr, f, M, DFF_, DM);
        gemm_tc<2><<<dim3(DM/TBN, M/TBM), 256>>>(f, w2 + (size_t)i*DM*DFF_, b2 + i*DM, h, c, M, DM, DFF_);
        ln_k<<<M, DM>>>(c, ln2_g + i*DM, ln2_b + i*DM, h);

        if (i < 2) {
            wreorder_k<<<DM, DM>>>(dc_w + (size_t)i*DM*1536, wr);
            gemm_conv<<<dim3(DM/TBN, M/TBM), 256>>>(h, wr, dc_b + i*DM, c, lshift, L - 1);
            bnstat1_k<<<64, DM>>>(c, stats, M);
            bnstat2_k<<<1, DM>>>(stats, bn_g + i*DM, bn_b + i*DM, bnsc, bnsh, M);
            pool_k<<<dim3(L/2, BATCH), DM>>>(c, bnsc, bnsh, h, L);
            L /= 2;
            lshift -= 1;
        }
        idx_off += n;
    }

    final_k<<<BATCH, DM>>>(h, fln_g, fln_b, proj_w, proj_b, x, skip_w, skip_b, out, L);
}

// round 6
// speedup vs baseline: 3.1126x; 1.0652x over previous
#include <cuda_runtime.h>
#include <cuda_bf16.h>
#include <math.h>
#include <stdint.h>

#define BATCH 32
#define L0    2048
#define CIN   7
#define DM    512
#define DFF_  2048
#define NH    8
#define DH    64
#define POUT  96

// ---------------- scratch ----------------
__device__ __align__(128) float g_h[(size_t)BATCH*L0*DM];
__device__ __align__(128) float g_q[(size_t)BATCH*L0*DM];
__device__ __align__(128) float g_k[(size_t)BATCH*L0*DM];
__device__ __align__(128) float g_v[(size_t)BATCH*L0*DM];
__device__ __align__(128) float g_c[(size_t)BATCH*L0*DM];
__device__ __align__(128) float g_f[(size_t)BATCH*L0*DFF_];
__device__ __align__(128) float g_m[(size_t)BATCH*NH*L0];
__device__ __align__(128) int   g_top[BATCH*NH*64];
__device__ __align__(128) float g_vmean[BATCH*NH*DH];
__device__ __align__(128) int   g_idx[L0*38 + 1024*34 + 512*31];
__device__ __align__(128) float g_stats[2*64*DM];
__device__ __align__(128) float g_bnsc[DM];
__device__ __align__(128) float g_bnsh[DM];
__device__ __align__(128) float g_wr[DM*1536];
__device__ __align__(128) float g_woT[DM*DM];
__device__ __align__(128) float g_dt[(size_t)BATCH*NH*64*DH];
__device__ __align__(128) float g_cr[(size_t)BATCH*NH*64*DM];
__device__ __align__(128) int   g_flag[BATCH*NH*L0];
__device__ __align__(128) float g_base[BATCH*DM];

// ---------------- threefry2x32 ----------------
__host__ __device__ inline void tf2x32(unsigned k0, unsigned k1, unsigned c0, unsigned c1,
                                       unsigned& o0, unsigned& o1)
{
    unsigned ks0 = k0, ks1 = k1, ks2 = k0 ^ k1 ^ 0x1BD11BDAu;
    unsigned x0 = c0 + ks0, x1 = c1 + ks1;
#define TFR(r) { x0 += x1; x1 = (x1 << (r)) | (x1 >> (32 - (r))); x1 ^= x0; }
    TFR(13) TFR(15) TFR(26) TFR(6)   x0 += ks1; x1 += ks2 + 1u;
    TFR(17) TFR(29) TFR(16) TFR(24)  x0 += ks2; x1 += ks0 + 2u;
    TFR(13) TFR(15) TFR(26) TFR(6)   x0 += ks0; x1 += ks1 + 3u;
    TFR(17) TFR(29) TFR(16) TFR(24)  x0 += ks1; x1 += ks2 + 4u;
    TFR(13) TFR(15) TFR(26) TFR(6)   x0 += ks2; x1 += ks0 + 5u;
#undef TFR
    o0 = x0; o1 = x1;
}

__global__ void idx_k(unsigned ka, unsigned kb, int n, unsigned mask, int* __restrict__ out)
{
    int i = blockIdx.x * 256 + threadIdx.x;
    if (i >= n) return;
    unsigned v0, v1;
    tf2x32(ka, kb, 0u, (unsigned)i, v0, v1);
    out[i] = (int)((v0 ^ v1) & mask);
}

// ---------------- token conv + positional embedding ----------------
__global__ void tokconv_k(const float* __restrict__ x, const float* __restrict__ w,
                          float* __restrict__ h)
{
    int l = blockIdx.x, b = blockIdx.y;
    int d = threadIdx.x;
    __shared__ float sx[3][CIN];
    if (threadIdx.x < 21) {
        int t = threadIdx.x / 7, c = threadIdx.x % 7;
        int ls = l + t - 1; if (ls < 0) ls += L0; if (ls >= L0) ls -= L0;
        sx[t][c] = x[((size_t)b*L0 + ls)*CIN + c];
    }
    __syncthreads();
    float acc = 0.f;
    const float* wd = w + d*CIN*3;
#pragma unroll
    for (int c = 0; c < CIN; c++)
#pragma unroll
        for (int t = 0; t < 3; t++)
            acc += sx[t][c] * wd[c*3 + t];
    int i2 = d & ~1;
    float freq = expf((float)i2 * (-9.210340371976184f / 512.0f));
    float ang = (float)l * freq;
    float pe = (d & 1) ? cosf(ang) : sinf(ang);
    h[((size_t)b*L0 + l)*DM + d] = acc + pe;
}

// ---------------- cp.async helpers ----------------
__device__ __forceinline__ void cp16(void* smem, const void* gptr)
{
    unsigned s = (unsigned)__cvta_generic_to_shared(smem);
    asm volatile("cp.async.cg.shared.global [%0], [%1], 16;\n" :: "r"(s), "l"(gptr));
}
__device__ __forceinline__ void cp_commit() { asm volatile("cp.async.commit_group;\n"); }
__device__ __forceinline__ void cp_wait2()  { asm volatile("cp.async.wait_group 2;\n"); }
__device__ __forceinline__ void cp_wait1()  { asm volatile("cp.async.wait_group 1;\n"); }
__device__ __forceinline__ void cp_wait0()  { asm volatile("cp.async.wait_group 0;\n"); }

__device__ __forceinline__ uint32_t ldcvt(float v)
{
    asm("cvt.rna.tf32.f32 %0, %0;" : "+f"(v));
    return __float_as_uint(v);
}

__device__ __forceinline__ void mma8(float* d, const uint32_t* a, const uint32_t* b)
{
    asm volatile(
        "mma.sync.aligned.m16n8k8.row.col.f32.tf32.tf32.f32 "
        "{%0,%1,%2,%3},{%4,%5,%6,%7},{%8,%9},{%0,%1,%2,%3};"
        : "+f"(d[0]), "+f"(d[1]), "+f"(d[2]), "+f"(d[3])
        : "r"(a[0]), "r"(a[1]), "r"(a[2]), "r"(a[3]), "r"(b[0]), "r"(b[1]));
}

#define TBM 128
#define TBN 128
#define TBK 16
#define SPAD 4
#define NSTG 3

// ---------------- tf32 GEMM, cp.async 3-stage ----------------
// MODE: 0 plain+bias, 1 bias+gelu(exact), 2 bias+residual
template<int MODE>
__global__ __launch_bounds__(256) void gemm_tc(
    const float* __restrict__ A, const float* __restrict__ W,
    const float* __restrict__ bias, const float* __restrict__ R,
    float* __restrict__ C, int M, int N, int K)
{
    __shared__ __align__(16) float As[NSTG][TBM][TBK + SPAD];
    __shared__ __align__(16) float Ws[NSTG][TBN][TBK + SPAD];
    int tid = threadIdx.x;
    int wid = tid >> 5, lane = tid & 31;
    int m0 = blockIdx.y * TBM, n0 = blockIdx.x * TBN;
    int wm = (wid >> 2) * 64, wn = (wid & 3) * 32;
    int lrow = tid >> 2, lcol = (tid & 3) * 4;
    int qr = lane >> 2, rt = lane & 3;
    float acc[4][4][4] = {};
    const float* Ap = A + (size_t)(m0 + lrow)*K + lcol;
    const float* Wp = W + (size_t)(n0 + lrow)*K + lcol;
    int T = K / TBK;

    auto issue = [&](int t) {
        int s = t % NSTG;
        const float* Ap2 = Ap + (size_t)t*TBK;
        const float* Wp2 = Wp + (size_t)t*TBK;
        cp16(&As[s][lrow][lcol],      Ap2);
        cp16(&As[s][lrow + 64][lcol], Ap2 + (size_t)64*K);
        cp16(&Ws[s][lrow][lcol],      Wp2);
        cp16(&Ws[s][lrow + 64][lcol], Wp2 + (size_t)64*K);
        cp_commit();
    };

    issue(0);
    if (T > 1) issue(1);

    for (int t = 0; t < T; t++) {
        if (t + 2 < T) { issue(t + 2); cp_wait2(); }
        else if (t + 1 < T) cp_wait1();
        else cp_wait0();
        __syncthreads();
        int s = t % NSTG;
#pragma unroll
        for (int ks = 0; ks < 2; ks++) {
            int kb = ks * 8;
            uint32_t af[4][4], bf[4][2];
#pragma unroll
            for (int mi = 0; mi < 4; mi++) {
                int r = wm + mi*16 + qr;
                af[mi][0] = ldcvt(As[s][r    ][kb + rt    ]);
                af[mi][1] = ldcvt(As[s][r + 8][kb + rt    ]);
                af[mi][2] = ldcvt(As[s][r    ][kb + rt + 4]);
                af[mi][3] = ldcvt(As[s][r + 8][kb + rt + 4]);
            }
#pragma unroll
            for (int ni = 0; ni < 4; ni++) {
                int c = wn + ni*8 + qr;
                bf[ni][0] = ldcvt(Ws[s][c][kb + rt    ]);
                bf[ni][1] = ldcvt(Ws[s][c][kb + rt + 4]);
            }
#pragma unroll
            for (int mi = 0; mi < 4; mi++)
#pragma unroll
                for (int ni = 0; ni < 4; ni++)
                    mma8(acc[mi][ni], af[mi], bf[ni]);
        }
        __syncthreads();
    }

#pragma unroll
    for (int mi = 0; mi < 4; mi++) {
        int r = m0 + wm + mi*16 + qr;
#pragma unroll
        for (int ni = 0; ni < 4; ni++) {
            int c = n0 + wn + ni*8 + rt*2;
            float b0 = bias[c], b1 = bias[c+1];
#pragma unroll
            for (int half = 0; half < 2; half++) {
                int rr = r + half*8;
                float v0 = acc[mi][ni][half*2+0] + b0;
                float v1 = acc[mi][ni][half*2+1] + b1;
                if (MODE == 1) {
                    v0 = 0.5f * v0 * (1.0f + erff(v0 * 0.7071067811865475f));
                    v1 = 0.5f * v1 * (1.0f + erff(v1 * 0.7071067811865475f));
                }
                if (MODE == 2) {
                    v0 += R[(size_t)rr*N + c];
                    v1 += R[(size_t)rr*N + c + 1];
                }
                *(float2*)&C[(size_t)rr*N + c] = make_float2(v0, v1);
            }
        }
    }
}

// ---------------- conv weight reorder: wr[n][t*512+c] = w[n][c*3+t] ----------------
__global__ void wreorder_k(const float* __restrict__ w, float* __restrict__ wr)
{
    int n = blockIdx.x, c = threadIdx.x;
#pragma unroll
    for (int t = 0; t < 3; t++)
        wr[(size_t)n*1536 + t*512 + c] = w[(size_t)n*1536 + c*3 + t];
}

// ---------------- direct circular-conv GEMM (K=1536), 3-stage ----------------
__global__ __launch_bounds__(256) void gemm_conv(
    const float* __restrict__ Hsrc, const float* __restrict__ W,
    const float* __restrict__ bias, float* __restrict__ C,
    int lshift, int Lmask)
{
    const int K = 1536, N = DM;
    __shared__ __align__(16) float As[NSTG][TBM][TBK + SPAD];
    __shared__ __align__(16) float Ws[NSTG][TBN][TBK + SPAD];
    int tid = threadIdx.x;
    int wid = tid >> 5, lane = tid & 31;
    int m0 = blockIdx.y * TBM, n0 = blockIdx.x * TBN;
    int wm = (wid >> 2) * 64, wn = (wid & 3) * 32;
    int lrow = tid >> 2, lcol = (tid & 3) * 4;
    int qr = lane >> 2, rt = lane & 3;
    float acc[4][4][4] = {};
    int m1 = m0 + lrow, m2 = m0 + lrow + 64;
    int b1 = m1 >> lshift, l1 = m1 & Lmask;
    int b2 = m2 >> lshift, l2 = m2 & Lmask;
    const float* Wp = W + (size_t)(n0 + lrow)*K + lcol;
    int T = K / TBK;

    auto issueA = [&](int t) {
        int s = t % NSTG;
        int kt = t * TBK;
        int tt = kt >> 9;
        int cc = (kt & 511) + lcol;
        int ls1 = (l1 + tt - 1 + (Lmask+1)) & Lmask;
        int ls2 = (l2 + tt - 1 + (Lmask+1)) & Lmask;
        cp16(&As[s][lrow][lcol],      Hsrc + ((size_t)(b1 << lshift) + ls1)*DM + cc);
        cp16(&As[s][lrow + 64][lcol], Hsrc + ((size_t)(b2 << lshift) + ls2)*DM + cc);
        cp16(&Ws[s][lrow][lcol],      Wp + (size_t)t*TBK);
        cp16(&Ws[s][lrow + 64][lcol], Wp + (size_t)t*TBK + (size_t)64*K);
        cp_commit();
    };

    issueA(0);
    issueA(1);
    for (int t = 0; t < T; t++) {
        if (t + 2 < T) { issueA(t + 2); cp_wait2(); }
        else if (t + 1 < T) cp_wait1();
        else cp_wait0();
        __syncthreads();
        int s = t % NSTG;
#pragma unroll
        for (int ks = 0; ks < 2; ks++) {
            int kb = ks * 8;
            uint32_t af[4][4], bf[4][2];
#pragma unroll
            for (int mi = 0; mi < 4; mi++) {
                int r = wm + mi*16 + qr;
                af[mi][0] = ldcvt(As[s][r    ][kb + rt    ]);
                af[mi][1] = ldcvt(As[s][r + 8][kb + rt    ]);
                af[mi][2] = ldcvt(As[s][r    ][kb + rt + 4]);
                af[mi][3] = ldcvt(As[s][r + 8][kb + rt + 4]);
            }
#pragma unroll
            for (int ni = 0; ni < 4; ni++) {
                int c = wn + ni*8 + qr;
                bf[ni][0] = ldcvt(Ws[s][c][kb + rt    ]);
                bf[ni][1] = ldcvt(Ws[s][c][kb + rt + 4]);
            }
#pragma unroll
            for (int mi = 0; mi < 4; mi++)
#pragma unroll
                for (int ni = 0; ni < 4; ni++)
                    mma8(acc[mi][ni], af[mi], bf[ni]);
        }
        __syncthreads();
    }

#pragma unroll
    for (int mi = 0; mi < 4; mi++) {
        int r = m0 + wm + mi*16 + qr;
#pragma unroll
        for (int ni = 0; ni < 4; ni++) {
            int c = n0 + wn + ni*8 + rt*2;
            float b0 = bias[c], b1v = bias[c+1];
#pragma unroll
            for (int half = 0; half < 2; half++) {
                int rr = r + half*8;
                *(float2*)&C[(size_t)rr*N + c] =
                    make_float2(acc[mi][ni][half*2+0] + b0, acc[mi][ni][half*2+1] + b1v);
            }
        }
    }
}

// ---------------- ProbSparse: sampled m = max - mean ----------------
__global__ void sample_m_k(const float* __restrict__ Q, const float* __restrict__ Km,
                           const int* __restrict__ idx, float* __restrict__ Mout,
                           int L, int U)
{
    int b = blockIdx.z, h = blockIdx.y;
    int w = threadIdx.x >> 5, lane = threadIdx.x & 31;
    int l = blockIdx.x * 8 + w;
    float2 q2 = *(const float2*)(Q + ((size_t)b*L + l)*DM + h*DH + 2*lane);
    float mx = -INFINITY, sm = 0.f;
    const int* ip = idx + (size_t)l * U;
    for (int j = 0; j < U; j++) {
        int r = ip[j];
        float2 k2 = *(const float2*)(Km + ((size_t)b*L + r)*DM + h*DH + 2*lane);
        float p = q2.x*k2.x + q2.y*k2.y;
#pragma unroll
        for (int o = 16; o > 0; o >>= 1) p += __shfl_xor_sync(0xffffffffu, p, o);
        mx = fmaxf(mx, p); sm += p;
    }
    if (lane == 0) Mout[((size_t)b*NH + h)*L + l] = mx - sm / (float)U;
}

// ---------------- iterative top-u per (b,h) ----------------
__global__ void topk_k(const float* __restrict__ Min, int* __restrict__ top, int L, int U)
{
    __shared__ float sv[2048];
    __shared__ float rv[256];
    __shared__ int   ri[256];
    int bh = blockIdx.x, tid = threadIdx.x;
    const float* mp = Min + (size_t)bh * L;
    for (int i = tid; i < L; i += 256) sv[i] = mp[i];
    __syncthreads();
    for (int t = 0; t < U; t++) {
        float bv = -INFINITY; int bi = 0x7fffffff;
        for (int i = tid; i < L; i += 256) {
            float v = sv[i];
            if (v > bv || (v == bv && i < bi)) { bv = v; bi = i; }
        }
        rv[tid] = bv; ri[tid] = bi;
        __syncthreads();
        for (int s = 128; s > 0; s >>= 1) {
            if (tid < s) {
                if (rv[tid+s] > rv[tid] || (rv[tid+s] == rv[tid] && ri[tid+s] < ri[tid])) {
                    rv[tid] = rv[tid+s]; ri[tid] = ri[tid+s];
                }
            }
            __syncthreads();
        }
        if (tid == 0) { top[(size_t)bh*U + t] = ri[0]; sv[ri[0]] = -INFINITY; }
        __syncthreads();
    }
}

// ---------------- mean of V over L per (b,h,d) ----------------
__global__ void vmean_k(const float* __restrict__ V, float* __restrict__ out, int L)
{
    int b = blockIdx.y, h = blockIdx.x;
    int tid = threadIdx.x;
    int d = tid & 63, g = tid >> 6;
    __shared__ float red[4][64];
    float s = 0.f;
    for (int l = g; l < L; l += 4)
        s += V[((size_t)b*L + l)*DM + h*DH + d];
    red[g][d] = s;
    __syncthreads();
    if (g == 0)
        out[((size_t)b*NH + h)*DH + d] = (red[0][d]+red[1][d]+red[2][d]+red[3][d]) / (float)L;
}

// ---------------- flash attention for top-u queries; writes DELTA = ctx_top - vmean ----------------
#define ATILE 64
__global__ __launch_bounds__(256) void attn_flash_k(
    const float* __restrict__ Q, const float* __restrict__ Km,
    const float* __restrict__ V, const int* __restrict__ top,
    const float* __restrict__ vm, float* __restrict__ dt, int L, int U)
{
    __shared__ float Ks[ATILE][DH];
    __shared__ float Vs[ATILE][DH];
    int h = blockIdx.x, b = blockIdx.y;
    int tid = threadIdx.x, w = tid >> 5, lane = tid & 31;

    float2 qv[5]; bool act[5];
    float mx[5], ss[5]; float2 acc[5];
#pragma unroll
    for (int i = 0; i < 5; i++) {
        int j = w + 8*i;
        act[i] = (j < U);
        int t = act[i] ? top[((size_t)b*NH + h)*U + j] : 0;
        qv[i] = *(const float2*)(Q + ((size_t)b*L + t)*DM + h*DH + 2*lane);
        mx[i] = -INFINITY; ss[i] = 0.f; acc[i] = make_float2(0.f, 0.f);
    }
    const float* Kb = Km + (size_t)b*L*DM + h*DH;
    const float* Vb = V  + (size_t)b*L*DM + h*DH;

    for (int r0 = 0; r0 < L; r0 += ATILE) {
        __syncthreads();
        for (int i = tid; i < ATILE*16; i += 256) {
            int r = i >> 4, c4 = (i & 15) * 4;
            *(float4*)&Ks[r][c4] = *(const float4*)(Kb + (size_t)(r0 + r)*DM + c4);
            *(float4*)&Vs[r][c4] = *(const float4*)(Vb + (size_t)(r0 + r)*DM + c4);
        }
        __syncthreads();
        for (int r = 0; r < ATILE; r++) {
            float2 kv = *(float2*)&Ks[r][2*lane];
            float2 vv = *(float2*)&Vs[r][2*lane];
#pragma unroll
            for (int i = 0; i < 5; i++) {
                float p = qv[i].x*kv.x + qv[i].y*kv.y;
                p += __shfl_xor_sync(0xffffffffu, p, 16);
                p += __shfl_xor_sync(0xffffffffu, p, 8);
                p += __shfl_xor_sync(0xffffffffu, p, 4);
                p += __shfl_xor_sync(0xffffffffu, p, 2);
                p += __shfl_xor_sync(0xffffffffu, p, 1);
                p *= 0.125f;
                float mn = fmaxf(mx[i], p);
                float corr = __expf(mx[i] - mn);
                float e = __expf(p - mn);
                ss[i] = ss[i]*corr + e;
                acc[i].x = acc[i].x*corr + e*vv.x;
                acc[i].y = acc[i].y*corr + e*vv.y;
                mx[i] = mn;
            }
        }
    }
    float2 vmv = *(const float2*)(vm + ((size_t)b*NH + h)*DH + 2*lane);
#pragma unroll
    for (int i = 0; i < 5; i++) {
        if (!act[i]) continue;
        int j = w + 8*i;
        float inv = 1.0f / ss[i];
        *(float2*)(dt + (((size_t)(b*NH + h))*64 + j)*DH + 2*lane) =
            make_float2(acc[i].x*inv - vmv.x, acc[i].y*inv - vmv.y);
    }
}

// ---------------- Wo transpose (512x512): woT[k][n] = wo[n][k] ----------------
__global__ void transpose_k(const float* __restrict__ in, float* __restrict__ out)
{
    __shared__ float t[32][33];
    int x = blockIdx.x*32 + threadIdx.x;
    int y = blockIdx.y*32 + threadIdx.y;
#pragma unroll
    for (int i = 0; i < 32; i += 8) t[threadIdx.y + i][threadIdx.x] = in[(size_t)(y + i)*DM + x];
    __syncthreads();
    x = blockIdx.y*32 + threadIdx.x;
    y = blockIdx.x*32 + threadIdx.y;
#pragma unroll
    for (int i = 0; i < 32; i += 8) out[(size_t)(y + i)*DM + x] = t[threadIdx.x][threadIdx.y + i];
}

// ---------------- corrections: cr[b,h,j][n] = sum_d dt[b,h,j][d] * woT[h*64+d][n] ----------------
__global__ __launch_bounds__(256) void corr_k(
    const float* __restrict__ dt, const float* __restrict__ woT,
    float* __restrict__ cr, int U)
{
    int h = blockIdx.x, b = blockIdx.y;
    int tid = threadIdx.x;
    __shared__ float dl[4][DH];
    for (int j0 = 0; j0 < U; j0 += 4) {
        for (int i = tid; i < 4*DH; i += 256) {
            int jj = i >> 6, dd = i & 63;
            int j = j0 + jj;
            dl[jj][dd] = (j < U) ? dt[(((size_t)(b*NH + h))*64 + j)*DH + dd] : 0.f;
        }
        __syncthreads();
        float a0[4] = {}, a1[4] = {};
        for (int d = 0; d < DH; d++) {
            float w0 = woT[(size_t)(h*DH + d)*DM + tid];
            float w1 = woT[(size_t)(h*DH + d)*DM + tid + 256];
#pragma unroll
            for (int jj = 0; jj < 4; jj++) {
                a0[jj] += dl[jj][d] * w0;
                a1[jj] += dl[jj][d] * w1;
            }
        }
#pragma unroll
        for (int jj = 0; jj < 4; jj++) {
            int j = j0 + jj;
            if (j < U) {
                cr[(((size_t)(b*NH + h))*64 + j)*DM + tid]       = a0[jj];
                cr[(((size_t)(b*NH + h))*64 + j)*DM + tid + 256] = a1[jj];
            }
        }
        __syncthreads();
    }
}

// ---------------- base[b][n] = bo[n] + sum_k vmc[b][k]*woT[k][n] ----------------
__global__ void base_k(const float* __restrict__ vm, const float* __restrict__ woT,
                       const float* __restrict__ bo, float* __restrict__ base)
{
    int b = blockIdx.x, n = threadIdx.x;
    __shared__ float vs[DM];
    vs[n] = vm[((size_t)b*NH + (n >> 6))*DH + (n & 63)];
    __syncthreads();
    float acc = bo[n];
    for (int k = 0; k < DM; k++)
        acc += vs[k] * woT[(size_t)k*DM + n];
    base[b*DM + n] = acc;
}

// ---------------- flags ----------------
__global__ void flaginit_k(int* __restrict__ flag, int n)
{
    int i = blockIdx.x * 256 + threadIdx.x;
    if (i < n) flag[i] = -1;
}
__global__ void flagset_k(const int* __restrict__ top, int* __restrict__ flag, int L, int U)
{
    int i = blockIdx.x * 256 + threadIdx.x;
    if (i >= BATCH*NH*U) return;
    int bh = i / U, j = i % U;
    flag[(size_t)bh*L + top[(size_t)bh*U + j]] = j;
}

// ---------------- apply: h += base + scattered corrections ----------------
__global__ void apply_k(float* __restrict__ h, const float* __restrict__ base,
                        const float* __restrict__ cr, const int* __restrict__ flag, int L)
{
    int l = blockIdx.x, b = blockIdx.y;
    int n = threadIdx.x;
    __shared__ int fj[NH];
    if (n < NH) fj[n] = flag[((size_t)(b*NH + n))*L + l];
    __syncthreads();
    size_t row = ((size_t)b*L + l)*DM;
    float val = h[row + n] + base[b*DM + n];
#pragma unroll
    for (int hh = 0; hh < NH; hh++) {
        int j = fj[hh];
        if (j >= 0) val += cr[(((size_t)(b*NH + hh))*64 + j)*DM + n];
    }
    h[row + n] = val;
}

// ---------------- LayerNorm (shuffle reduction) ----------------
__device__ __forceinline__ float wsum(float v)
{
#pragma unroll
    for (int o = 16; o > 0; o >>= 1) v += __shfl_xor_sync(0xffffffffu, v, o);
    return v;
}

__global__ void ln_k(const float* __restrict__ in, const float* __restrict__ g,
                     const float* __restrict__ be, float* __restrict__ out)
{
    __shared__ float ws[16];
    __shared__ float s_mu, s_rstd;
    int d = threadIdx.x; size_t row = blockIdx.x;
    int w = d >> 5, lane = d & 31;
    float v = in[row*DM + d];
    float s = wsum(v);
    if (lane == 0) ws[w] = s;
    __syncthreads();
    if (w == 0) {
        float t = (lane < 16) ? ws[lane] : 0.f;
        t = wsum(t);
        if (lane == 0) s_mu = t * (1.0f/512.0f);
    }
    __syncthreads();
    float x = v - s_mu;
    s = wsum(x*x);
    if (lane == 0) ws[w] = s;
    __syncthreads();
    if (w == 0) {
        float t = (lane < 16) ? ws[lane] : 0.f;
        t = wsum(t);
        if (lane == 0) s_rstd = rsqrtf(t * (1.0f/512.0f) + 1e-5f);
    }
    __syncthreads();
    out[row*DM + d] = x * s_rstd * g[d] + be[d];
}

// ---------------- BatchNorm stats ----------------
__global__ void bnstat1_k(const float* __restrict__ y, float* __restrict__ st, int M)
{
    int d = threadIdx.x, chunk = blockIdx.x;
    int rows = M / 64;
    const float* p = y + (size_t)chunk * rows * DM;
    float s = 0.f, s2 = 0.f;
    for (int r = 0; r < rows; r++) { float v = p[(size_t)r*DM + d]; s += v; s2 += v*v; }
    st[chunk*DM + d] = s;
    st[64*DM + chunk*DM + d] = s2;
}

__global__ void bnstat2_k(const float* __restrict__ st, const float* __restrict__ g,
                          const float* __restrict__ be, float* __restrict__ sc,
                          float* __restrict__ sh, int M)
{
    int d = threadIdx.x;
    float s = 0.f, s2 = 0.f;
    for (int c = 0; c < 64; c++) { s += st[c*DM + d]; s2 += st[64*DM + c*DM + d]; }
    float mu = s / (float)M;
    float var = s2 / (float)M - mu*mu;
    float scale = g[d] * rsqrtf(var + 1e-5f);
    sc[d] = scale; sh[d] = be[d] - mu*scale;
}

// ---------------- BN + ELU + maxpool ----------------
__global__ void pool_k(const float* __restrict__ y, const float* __restrict__ sc,
                       const float* __restrict__ sh, float* __restrict__ out, int L)
{
    int d = threadIdx.x, j = blockIdx.x, b = blockIdx.y;
    int Lh = L / 2;
    float scl = sc[d], shf = sh[d];
    float m = -INFINITY;
#pragma unroll
    for (int t = 0; t < 3; t++) {
        int ly = 2*j - 1 + t;
        if (ly < 0 || ly >= L) continue;
        float v = y[((size_t)b*L + ly)*DM + d] * scl + shf;
        v = v > 0.f ? v : expm1f(v);
        m = fmaxf(m, v);
    }
    out[((size_t)b*Lh + j)*DM + d] = m;
}

// ---------------- final LN(row L-1) @ proj + skip ----------------
__global__ void final_k(const float* __restrict__ h, const float* __restrict__ g,
                        const float* __restrict__ be, const float* __restrict__ pw,
                        const float* __restrict__ pb, const float* __restrict__ x,
                        const float* __restrict__ sw, const float* __restrict__ sb,
                        float* __restrict__ out, int L)
{
    __shared__ float ws[16];
    __shared__ float sval[512];
    __shared__ float s_mu, s_rstd;
    int d = threadIdx.x, b = blockIdx.x;
    int w = d >> 5, lane = d & 31;
    float v = h[((size_t)b*L + (L-1))*DM + d];
    float s = wsum(v);
    if (lane == 0) ws[w] = s;
    __syncthreads();
    if (w == 0) {
        float t = (lane < 16) ? ws[lane] : 0.f;
        t = wsum(t);
        if (lane == 0) s_mu = t * (1.0f/512.0f);
    }
    __syncthreads();
    float xv = v - s_mu;
    s = wsum(xv*xv);
    if (lane == 0) ws[w] = s;
    __syncthreads();
    if (w == 0) {
        float t = (lane < 16) ? ws[lane] : 0.f;
        t = wsum(t);
        if (lane == 0) s_rstd = rsqrtf(t * (1.0f/512.0f) + 1e-5f);
    }
    __syncthreads();
    sval[d] = xv * s_rstd * g[d] + be[d];
    __syncthreads();
    if (d < POUT) {
        float acc = pb[d];
        for (int kk = 0; kk < 512; kk++) acc += sval[kk] * pw[d*512 + kk];
        float sk = sb[d];
        for (int cc = 0; cc < CIN; cc++)
            sk += x[((size_t)b*L0 + (L0-1))*CIN + cc] * sw[d*CIN + cc];
        out[b*POUT + d] = acc + sk;
    }
}

extern "C" void kernel_launch(void* const* d_in, const int* in_sizes, int n_in,
                              void* d_out, int out_size)
{
    (void)in_sizes; (void)n_in; (void)out_size;
    const float* x       = (const float*)d_in[0];
    const float* skip_w  = (const float*)d_in[1];
    const float* skip_b  = (const float*)d_in[2];
    const float* tconv_w = (const float*)d_in[3];
    const float* wq = (const float*)d_in[4];  const float* bq = (const float*)d_in[5];
    const float* wk = (const float*)d_in[6];  const float* bk = (const float*)d_in[7];
    const float* wv = (const float*)d_in[8];  const float* bv = (const float*)d_in[9];
    const float* wo = (const float*)d_in[10]; const float* bo = (const float*)d_in[11];
    const float* w1 = (const float*)d_in[12]; const float* b1 = (const float*)d_in[13];
    const float* w2 = (const float*)d_in[14]; const float* b2 = (const float*)d_in[15];
    const float* ln1_g = (const float*)d_in[16]; const float* ln1_b = (const float*)d_in[17];
    const float* ln2_g = (const float*)d_in[18]; const float* ln2_b = (const float*)d_in[19];
    const float* dc_w = (const float*)d_in[20]; const float* dc_b = (const float*)d_in[21];
    const float* bn_g = (const float*)d_in[22]; const float* bn_b = (const float*)d_in[23];
    const float* fln_g = (const float*)d_in[24]; const float* fln_b = (const float*)d_in[25];
    const float* proj_w = (const float*)d_in[26]; const float* proj_b = (const float*)d_in[27];
    float* out = (float*)d_out;

    float *h, *q, *k, *v, *c, *f, *m, *vm, *stats, *bnsc, *bnsh, *wr, *woT, *dt, *cr, *base;
    int *idx, *topI, *flag;
    cudaGetSymbolAddress((void**)&h, g_h);
    cudaGetSymbolAddress((void**)&q, g_q);
    cudaGetSymbolAddress((void**)&k, g_k);
    cudaGetSymbolAddress((void**)&v, g_v);
    cudaGetSymbolAddress((void**)&c, g_c);
    cudaGetSymbolAddress((void**)&f, g_f);
    cudaGetSymbolAddress((void**)&m, g_m);
    cudaGetSymbolAddress((void**)&vm, g_vmean);
    cudaGetSymbolAddress((void**)&stats, g_stats);
    cudaGetSymbolAddress((void**)&bnsc, g_bnsc);
    cudaGetSymbolAddress((void**)&bnsh, g_bnsh);
    cudaGetSymbolAddress((void**)&wr, g_wr);
    cudaGetSymbolAddress((void**)&woT, g_woT);
    cudaGetSymbolAddress((void**)&dt, g_dt);
    cudaGetSymbolAddress((void**)&cr, g_cr);
    cudaGetSymbolAddress((void**)&base, g_base);
    cudaGetSymbolAddress((void**)&idx, g_idx);
    cudaGetSymbolAddress((void**)&topI, g_top);
    cudaGetSymbolAddress((void**)&flag, g_flag);

    tokconv_k<<<dim3(L0, BATCH), DM>>>(x, tconv_w, h);

    int L = L0;
    int lshift = 11;
    const int Uarr[3] = {38, 34, 31};
    int idx_off = 0;
    for (int i = 0; i < 3; i++) {
        int U = Uarr[i];
        int M = BATCH * L;
        unsigned fk0, fk1, s2a, s2b;
        tf2x32(0u, 42u, 0u, (unsigned)i, fk0, fk1);
        tf2x32(fk0, fk1, 0u, 1u, s2a, s2b);
        int n = L * U;
        idx_k<<<(n + 255)/256, 256>>>(s2a, s2b, n, (unsigned)(L - 1), idx + idx_off);

        gemm_tc<0><<<dim3(DM/TBN, M/TBM), 256>>>(h, wq + (size_t)i*DM*DM, bq + i*DM, nullptr, q, M, DM, DM);
        gemm_tc<0><<<dim3(DM/TBN, M/TBM), 256>>>(h, wk + (size_t)i*DM*DM, bk + i*DM, nullptr, k, M, DM, DM);
        gemm_tc<0><<<dim3(DM/TBN, M/TBM), 256>>>(h, wv + (size_t)i*DM*DM, bv + i*DM, nullptr, v, M, DM, DM);

        sample_m_k<<<dim3(L/8, NH, BATCH), 256>>>(q, k, idx + idx_off, m, L, U);
        topk_k<<<BATCH*NH, 256>>>(m, topI, L, U);
        vmean_k<<<dim3(NH, BATCH), 256>>>(v, vm, L);
        attn_flash_k<<<dim3(NH, BATCH), 256>>>(q, k, v, topI, vm, dt, L, U);

        // WO projection via base + sparse corrections
        transpose_k<<<dim3(16, 16), dim3(32, 8)>>>(wo + (size_t)i*DM*DM, woT);
        corr_k<<<dim3(NH, BATCH), 256>>>(dt, woT, cr, U);
        base_k<<<BATCH, DM>>>(vm, woT, bo + i*DM, base);
        flaginit_k<<<(BATCH*NH*L + 255)/256, 256>>>(flag, BATCH*NH*L);
        flagset_k<<<(BATCH*NH*U + 255)/256, 256>>>(topI, flag, L, U);
        apply_k<<<dim3(L, BATCH), DM>>>(h, base, cr, flag, L);

        // FFN
        ln_k<<<M, DM>>>(h, ln1_g + i*DM, ln1_b + i*DM, c);
        gemm_tc<1><<<dim3(DFF_/TBN, M/TBM), 256>>>(c, w1 + (size_t)i*DFF_*DM, b1 + i*DFF_, nullptr, f, M, DFF_, DM);
        gemm_tc<2><<<dim3(DM/TBN, M/TBM), 256>>>(f, w2 + (size_t)i*DM*DFF_, b2 + i*DM, h, c, M, DM, DFF_);
        ln_k<<<M, DM>>>(c, ln2_g + i*DM, ln2_b + i*DM, h);

        if (i < 2) {
            wreorder_k<<<DM, DM>>>(dc_w + (size_t)i*DM*1536, wr);
            gemm_conv<<<dim3(DM/TBN, M/TBM), 256>>>(h, wr, dc_b + i*DM, c, lshift, L - 1);
            bnstat1_k<<<64, DM>>>(c, stats, M);
            bnstat2_k<<<1, DM>>>(stats, bn_g + i*DM, bn_b + i*DM, bnsc, bnsh, M);
            pool_k<<<dim3(L/2, BATCH), DM>>>(c, bnsc, bnsh, h, L);
            L /= 2;
            lshift -= 1;
        }
        idx_off += n;
    }

    final_k<<<BATCH, DM>>>(h, fln_g, fln_b, proj_w, proj_b, x, skip_w, skip_b, out, L);
}